// round 15
// baseline (speedup 1.0000x reference)
#include <cuda_runtime.h>
#include <cuda_bf16.h>
#include <mma.h>
#include <cstdint>

using namespace nvcuda;

#define NPIX 8192
#define NPTS 8192
#define NTOK 16384
#define NWIN 128
#define CAP  256
#define NCHUNK 32

// ---------------- scratch (device globals; no allocation) ----------------
__device__ __nv_bfloat16 g_imgh[2097152], g_imgl[2097152];
__device__ __nv_bfloat16 g_feath[NTOK * 128], g_featl[NTOK * 128];
__device__ float g_qkv [NTOK * 384];
__device__ __nv_bfloat16 g_oh[NPIX * 128], g_ol[NPIX * 128];
__device__ __nv_bfloat16 g_resh[NPIX * 128], g_resl[NPIX * 128];
__device__ __nv_bfloat16 g_wh[147456];
__device__ __nv_bfloat16 g_wl[147456];
__device__ int   g_ptw [NPTS];
__device__ int   g_hist[NCHUNK * NWIN];
__device__ int   g_win_tok[NWIN * CAP];
__device__ int   g_win_cnt[NWIN];

#define WOFF_CI  0
#define WOFF_QKV 32768
#define WOFF_PR  81920
#define WOFF_ODE 98304
#define WOFF_CO  114688

// ---------------- helpers ----------------
__device__ __forceinline__ uint32_t bf16x2_of(float hi, float lo) {
    uint32_t r; asm("cvt.rn.bf16x2.f32 %0, %1, %2;" : "=r"(r) : "f"(hi), "f"(lo)); return r;
}
__device__ __forceinline__ float bf16lo_f(uint32_t v) { return __uint_as_float(v << 16); }
__device__ __forceinline__ float bf16hi_f(uint32_t v) { return __uint_as_float(v & 0xffff0000u); }

__device__ __forceinline__ uint32_t smem_u32(const void* p) {
    uint32_t a;
    asm("{ .reg .u64 t; cvta.to.shared.u64 t, %1; cvt.u32.u64 %0, t; }" : "=r"(a) : "l"(p));
    return a;
}
__device__ __forceinline__ void cpa16(uint32_t s, const void* g) {
    asm volatile("cp.async.cg.shared.global [%0], [%1], 16;" :: "r"(s), "l"(g));
}
__device__ __forceinline__ void cp_commit() { asm volatile("cp.async.commit_group;" ::: "memory"); }
__device__ __forceinline__ void cp_wait1() { asm volatile("cp.async.wait_group 1;" ::: "memory"); }
__device__ __forceinline__ void cp_wait0() { asm volatile("cp.async.wait_group 0;" ::: "memory"); }

__device__ __forceinline__ void ldm4(uint32_t* r, uint32_t addr) {
    asm volatile("ldmatrix.sync.aligned.m8n8.x4.shared.b16 {%0,%1,%2,%3}, [%4];"
                 : "=r"(r[0]), "=r"(r[1]), "=r"(r[2]), "=r"(r[3]) : "r"(addr));
}
__device__ __forceinline__ void mma16816(float* d, const uint32_t* a, uint32_t b0, uint32_t b1) {
    asm volatile("mma.sync.aligned.m16n8k16.row.col.f32.bf16.bf16.f32 "
                 "{%0,%1,%2,%3}, {%4,%5,%6,%7}, {%8,%9}, {%0,%1,%2,%3};"
                 : "+f"(d[0]), "+f"(d[1]), "+f"(d[2]), "+f"(d[3])
                 : "r"(a[0]), "r"(a[1]), "r"(a[2]), "r"(a[3]), "r"(b0), "r"(b1));
}

// ============================================================================
// Merged prep: weights | points | wid/hist/pixel slots | image split
// ============================================================================
__global__ void prep(const float* __restrict__ wci, const float* __restrict__ wqkv,
                     const float* __restrict__ wpr, const float* __restrict__ wode,
                     const float* __restrict__ wco, const float* __restrict__ ptsf,
                     const int* __restrict__ uv, const float* __restrict__ img) {
    __shared__ int cnt[NWIN];
    int bid = blockIdx.x, t = threadIdx.x;
    if (bid < 576) {
        int i = bid * 256 + t;
        if (i >= 147456) return;
        float x;
        if (i < WOFF_QKV)      x = wci [i];
        else if (i < WOFF_PR)  x = wqkv[i - WOFF_QKV];
        else if (i < WOFF_ODE) x = wpr [i - WOFF_PR];
        else if (i < WOFF_CO)  x = wode[i - WOFF_ODE];
        else                   x = wco [i - WOFF_CO];
        __nv_bfloat16 h = __float2bfloat16(x);
        g_wh[i] = h;
        g_wl[i] = __float2bfloat16(x - __bfloat162float(h));
    } else if (bid < 1600) {
        int i = (bid - 576) * 256 + t;
        float4 v = ((const float4*)ptsf)[i];
        uint32_t h0 = bf16x2_of(v.y, v.x);
        uint32_t h1 = bf16x2_of(v.w, v.z);
        uint32_t l0 = bf16x2_of(v.y - bf16hi_f(h0), v.x - bf16lo_f(h0));
        uint32_t l1 = bf16x2_of(v.w - bf16hi_f(h1), v.z - bf16lo_f(h1));
        uint32_t* fh = (uint32_t*)g_feath;
        uint32_t* fl = (uint32_t*)g_featl;
        int o = 524288 + 2 * i;
        fh[o] = h0; fh[o + 1] = h1;
        fl[o] = l0; fl[o + 1] = l1;
    } else if (bid < 1632) {
        int c = bid - 1600;
        int i = c * 256 + t;
        if (t < NWIN) cnt[t] = 0;
        __syncthreads();
        int b = uv[3 * i] & 1;
        int u = uv[3 * i + 1] & 63;
        int v = uv[3 * i + 2] & 63;
        int wid = ((b * 8 + (v >> 3)) << 3) + (u >> 3);
        g_ptw[i] = wid;
        atomicAdd(&cnt[wid], 1);
        {
            int w = i >> 6, r = i & 63;
            int wb = w >> 6, wy = (w >> 3) & 7, wx = w & 7;
            int pv = wy * 8 + (r >> 3), pu = wx * 8 + (r & 7);
            g_win_tok[w * CAP + r] = wb * 4096 + pv * 64 + pu;
        }
        __syncthreads();
        if (t < NWIN) g_hist[c * NWIN + t] = cnt[t];
    } else {
        int i = (bid - 1632) * 256 + t;
        float4 v = ((const float4*)img)[i];
        uint32_t h0 = bf16x2_of(v.y, v.x);
        uint32_t h1 = bf16x2_of(v.w, v.z);
        uint32_t l0 = bf16x2_of(v.y - bf16hi_f(h0), v.x - bf16lo_f(h0));
        uint32_t l1 = bf16x2_of(v.w - bf16hi_f(h1), v.z - bf16lo_f(h1));
        uint32_t* ih = (uint32_t*)g_imgh;
        uint32_t* il = (uint32_t*)g_imgl;
        int o = 2 * i;
        ih[o] = h0; ih[o + 1] = h1;
        il[o] = l0; il[o + 1] = l1;
    }
}

// ============================================================================
// MID kernel: scatter | conv_in | point-KV merged (mutually independent).
// ============================================================================
#define MID_SMEM 92160

__global__ __launch_bounds__(256) void mid_kernel(
        const __nv_bfloat16* __restrict__ iAh, const __nv_bfloat16* __restrict__ iAl,
        const __nv_bfloat16* __restrict__ cBh, const __nv_bfloat16* __restrict__ cBl,
        const float* __restrict__ cbias,
        __nv_bfloat16* __restrict__ Ch, __nv_bfloat16* __restrict__ Cl,
        const __nv_bfloat16* __restrict__ pAh, const __nv_bfloat16* __restrict__ pAl,
        const __nv_bfloat16* __restrict__ kBh, const __nv_bfloat16* __restrict__ kBl,
        const float* __restrict__ kbias, float* __restrict__ Ckv) {
    extern __shared__ __align__(16) char sm[];
    const int bid = blockIdx.x;
    const int t = threadIdx.x;

    if (bid < 32) {
        __shared__ int cnt[NWIN];
        int lane = t & 31;
        int c = bid;
        int i = c * 256 + t;
        if (t < NWIN) {
            int run = 0;
            for (int cc = 0; cc < c; cc++) run += g_hist[cc * NWIN + t];
            cnt[t] = run;
            if (c == NCHUNK - 1) {
                int tot = 64 + run + g_hist[(NCHUNK - 1) * NWIN + t];
                g_win_cnt[t] = tot < CAP ? tot : CAP;
            }
        }
        __syncthreads();
        int wid = g_ptw[i];
        for (int wv = 0; wv < 8; wv++) {
            if ((t >> 5) == wv) {
                unsigned mask = __match_any_sync(0xffffffffu, wid);
                int prior = __popc(mask & ((1u << lane) - 1u));
                int base = cnt[wid];
                __syncwarp();
                int rank = 64 + base + prior;
                if (rank < CAP) g_win_tok[wid * CAP + rank] = NPIX + i;
                if (prior == 0) cnt[wid] = base + __popc(mask);
            }
            __syncthreads();
        }
    } else if (bid < 160) {
        const uint32_t smb = smem_u32(sm);
        const int w = t >> 5;
        const int bb = bid - 32;
        const int row0 = (bb >> 1) << 7, col0 = (bb & 1) << 6;
        const int b = row0 >> 12, hw0 = row0 & 4095;
        const int m0 = (w >> 1) << 5, n0 = (w & 1) << 5;
        const int K = 256, KT = 8;

        auto issue = [&](int kt, int stg) {
            int k0 = kt << 5;
            uint32_t sb = smb + (uint32_t)stg * 27648;
#pragma unroll
            for (int i2 = 0; i2 < 2; i2++) {
                int id = t + (i2 << 8);
                int kk = id >> 4, m8 = (id & 15) << 3;
                uint32_t so = (uint32_t)(kk * 136 + m8) << 1;
                size_t g = (size_t)b * 1048576 + (size_t)(k0 + kk) * 4096 + hw0 + m8;
                cpa16(sb + so,        iAh + g);
                cpa16(sb + 8704 + so, iAl + g);
            }
            {
                int r = t >> 2, k8 = (t & 3) << 3;
                uint32_t so = (uint32_t)(r * 40 + k8) << 1;
                cpa16(sb + 17408 + so, cBh + (size_t)(col0 + r) * K + k0 + k8);
                cpa16(sb + 22528 + so, cBl + (size_t)(col0 + r) * K + k0 + k8);
            }
            cp_commit();
        };

        wmma::fragment<wmma::accumulator, 16, 16, 16, float> acc[2][2];
#pragma unroll
        for (int mi = 0; mi < 2; mi++)
#pragma unroll
            for (int ni = 0; ni < 2; ni++)
                wmma::fill_fragment(acc[mi][ni], 0.f);

        issue(0, 0);
        issue(1, 1);
        for (int kt = 0; kt < KT; kt++) {
            if (kt + 1 < KT) cp_wait1(); else cp_wait0();
            __syncthreads();
            if (kt + 2 < KT) issue(kt + 2, (kt + 2) % 3);
            char* sb = sm + (kt % 3) * 27648;
            __nv_bfloat16* sAh = (__nv_bfloat16*)sb;
            __nv_bfloat16* sAl = (__nv_bfloat16*)(sb + 8704);
            __nv_bfloat16* sBh = (__nv_bfloat16*)(sb + 17408);
            __nv_bfloat16* sBl = (__nv_bfloat16*)(sb + 22528);
#pragma unroll
            for (int ks = 0; ks < 2; ks++) {
                wmma::fragment<wmma::matrix_a, 16, 16, 16, __nv_bfloat16, wmma::col_major> ah0, ah1, al0, al1;
                wmma::fragment<wmma::matrix_b, 16, 16, 16, __nv_bfloat16, wmma::col_major> bh0, bh1, bl0, bl1;
                wmma::load_matrix_sync(ah0, sAh + (size_t)ks * 16 * 136 + m0, 136);
                wmma::load_matrix_sync(ah1, sAh + (size_t)ks * 16 * 136 + m0 + 16, 136);
                wmma::load_matrix_sync(al0, sAl + (size_t)ks * 16 * 136 + m0, 136);
                wmma::load_matrix_sync(al1, sAl + (size_t)ks * 16 * 136 + m0 + 16, 136);
                wmma::load_matrix_sync(bh0, sBh + (size_t)n0 * 40 + ks * 16, 40);
                wmma::load_matrix_sync(bh1, sBh + (size_t)(n0 + 16) * 40 + ks * 16, 40);
                wmma::load_matrix_sync(bl0, sBl + (size_t)n0 * 40 + ks * 16, 40);
                wmma::load_matrix_sync(bl1, sBl + (size_t)(n0 + 16) * 40 + ks * 16, 40);

                wmma::mma_sync(acc[0][0], ah0, bh0, acc[0][0]);
                wmma::mma_sync(acc[0][1], ah0, bh1, acc[0][1]);
                wmma::mma_sync(acc[1][0], ah1, bh0, acc[1][0]);
                wmma::mma_sync(acc[1][1], ah1, bh1, acc[1][1]);
                wmma::mma_sync(acc[0][0], ah0, bl0, acc[0][0]);
                wmma::mma_sync(acc[0][1], ah0, bl1, acc[0][1]);
                wmma::mma_sync(acc[1][0], ah1, bl0, acc[1][0]);
                wmma::mma_sync(acc[1][1], ah1, bl1, acc[1][1]);
                wmma::mma_sync(acc[0][0], al0, bh0, acc[0][0]);
                wmma::mma_sync(acc[0][1], al0, bh1, acc[0][1]);
                wmma::mma_sync(acc[1][0], al1, bh0, acc[1][0]);
                wmma::mma_sync(acc[1][1], al1, bh1, acc[1][1]);
            }
        }
        __syncthreads();

        float* scratch = (float*)sm;
#pragma unroll
        for (int mi = 0; mi < 2; mi++)
#pragma unroll
            for (int ni = 0; ni < 2; ni++)
                wmma::store_matrix_sync(scratch + (size_t)(m0 + mi * 16) * 64 + n0 + ni * 16,
                                        acc[mi][ni], 64, wmma::mem_row_major);
        __syncthreads();

        int r = t >> 1, cc = (t & 1) << 5;
        uint32_t* ch32 = (uint32_t*)Ch;
        uint32_t* cl32 = (uint32_t*)Cl;
#pragma unroll
        for (int q = 0; q < 8; q++) {
            float4 v = *(float4*)(scratch + r * 64 + cc + q * 4);
            float4 bb2 = *(const float4*)(cbias + col0 + cc + q * 4);
            v.x += bb2.x; v.y += bb2.y; v.z += bb2.z; v.w += bb2.w;
            uint32_t h01 = bf16x2_of(v.y, v.x);
            uint32_t h23 = bf16x2_of(v.w, v.z);
            uint32_t l01 = bf16x2_of(v.y - bf16hi_f(h01), v.x - bf16lo_f(h01));
            uint32_t l23 = bf16x2_of(v.w - bf16hi_f(h23), v.z - bf16lo_f(h23));
            int o = (row0 + r) * 64 + ((col0 + cc) >> 1) + q * 2;
            ch32[o] = h01; ch32[o + 1] = h23;
            cl32[o] = l01; cl32[o + 1] = l23;
        }
    } else {
        const uint32_t smb = smem_u32(sm);
        const int w = t >> 5;
        const int bb = bid - 160;
        const int row0 = (bb >> 2) << 7, col0 = (bb & 3) << 6;
        const int m0 = (w >> 1) << 5, n0 = (w & 1) << 5;
        const int K = 128, KT = 4, ldc = 384;

        auto issue = [&](int kt, int stg) {
            int k0 = kt << 5;
            uint32_t sb = smb + (uint32_t)stg * 30720;
#pragma unroll
            for (int i2 = 0; i2 < 2; i2++) {
                int id = t + (i2 << 8);
                int r = id >> 2, k8 = (id & 3) << 3;
                uint32_t so = (uint32_t)(r * 40 + k8) << 1;
                cpa16(sb + so,         pAh + (size_t)(row0 + r) * K + k0 + k8);
                cpa16(sb + 10240 + so, pAl + (size_t)(row0 + r) * K + k0 + k8);
            }
            {
                int r = t >> 2, k8 = (t & 3) << 3;
                uint32_t so = (uint32_t)(r * 40 + k8) << 1;
                cpa16(sb + 20480 + so, kBh + (size_t)(col0 + r) * K + k0 + k8);
                cpa16(sb + 25600 + so, kBl + (size_t)(col0 + r) * K + k0 + k8);
            }
            cp_commit();
        };

        wmma::fragment<wmma::accumulator, 16, 16, 16, float> acc[2][2];
#pragma unroll
        for (int mi = 0; mi < 2; mi++)
#pragma unroll
            for (int ni = 0; ni < 2; ni++)
                wmma::fill_fragment(acc[mi][ni], 0.f);

        issue(0, 0);
        issue(1, 1);
        for (int kt = 0; kt < KT; kt++) {
            if (kt + 1 < KT) cp_wait1(); else cp_wait0();
            __syncthreads();
            if (kt + 2 < KT) issue(kt + 2, (kt + 2) % 3);
            char* sb = sm + (kt % 3) * 30720;
            __nv_bfloat16* sAh = (__nv_bfloat16*)sb;
            __nv_bfloat16* sAl = (__nv_bfloat16*)(sb + 10240);
            __nv_bfloat16* sBh = (__nv_bfloat16*)(sb + 20480);
            __nv_bfloat16* sBl = (__nv_bfloat16*)(sb + 25600);
#pragma unroll
            for (int ks = 0; ks < 2; ks++) {
                wmma::fragment<wmma::matrix_a, 16, 16, 16, __nv_bfloat16, wmma::row_major> ah0, ah1, al0, al1;
                wmma::fragment<wmma::matrix_b, 16, 16, 16, __nv_bfloat16, wmma::col_major> bh0, bh1, bl0, bl1;
                wmma::load_matrix_sync(ah0, sAh + (size_t)m0 * 40 + ks * 16, 40);
                wmma::load_matrix_sync(ah1, sAh + (size_t)(m0 + 16) * 40 + ks * 16, 40);
                wmma::load_matrix_sync(al0, sAl + (size_t)m0 * 40 + ks * 16, 40);
                wmma::load_matrix_sync(al1, sAl + (size_t)(m0 + 16) * 40 + ks * 16, 40);
                wmma::load_matrix_sync(bh0, sBh + (size_t)n0 * 40 + ks * 16, 40);
                wmma::load_matrix_sync(bh1, sBh + (size_t)(n0 + 16) * 40 + ks * 16, 40);
                wmma::load_matrix_sync(bl0, sBl + (size_t)n0 * 40 + ks * 16, 40);
                wmma::load_matrix_sync(bl1, sBl + (size_t)(n0 + 16) * 40 + ks * 16, 40);

                wmma::mma_sync(acc[0][0], ah0, bh0, acc[0][0]);
                wmma::mma_sync(acc[0][1], ah0, bh1, acc[0][1]);
                wmma::mma_sync(acc[1][0], ah1, bh0, acc[1][0]);
                wmma::mma_sync(acc[1][1], ah1, bh1, acc[1][1]);
                wmma::mma_sync(acc[0][0], ah0, bl0, acc[0][0]);
                wmma::mma_sync(acc[0][1], ah0, bl1, acc[0][1]);
                wmma::mma_sync(acc[1][0], ah1, bl0, acc[1][0]);
                wmma::mma_sync(acc[1][1], ah1, bl1, acc[1][1]);
                wmma::mma_sync(acc[0][0], al0, bh0, acc[0][0]);
                wmma::mma_sync(acc[0][1], al0, bh1, acc[0][1]);
                wmma::mma_sync(acc[1][0], al1, bh0, acc[1][0]);
                wmma::mma_sync(acc[1][1], al1, bh1, acc[1][1]);
            }
        }
        __syncthreads();

        float* scratch = (float*)sm;
#pragma unroll
        for (int mi = 0; mi < 2; mi++)
#pragma unroll
            for (int ni = 0; ni < 2; ni++)
                wmma::store_matrix_sync(scratch + (size_t)(m0 + mi * 16) * 64 + n0 + ni * 16,
                                        acc[mi][ni], 64, wmma::mem_row_major);
        __syncthreads();

        int r = t >> 1, cc = (t & 1) << 5;
#pragma unroll
        for (int q = 0; q < 8; q++) {
            float4 v = *(float4*)(scratch + r * 64 + cc + q * 4);
            float4 bb2 = *(const float4*)(kbias + col0 + cc + q * 4);
            v.x += bb2.x; v.y += bb2.y; v.z += bb2.z; v.w += bb2.w;
            *(float4*)(Ckv + (size_t)(row0 + r) * ldc + col0 + cc + q * 4) = v;
        }
    }
}

// ============================================================================
// pixel qkv GEMM: 3-stage pipelined, row-major A. Block 128x64.
// ============================================================================
#define GBF_SMEM 92160

__global__ __launch_bounds__(256) void bfgemm_bf(const __nv_bfloat16* __restrict__ Ah,
                                                 const __nv_bfloat16* __restrict__ Al,
                                                 const __nv_bfloat16* __restrict__ Bh,
                                                 const __nv_bfloat16* __restrict__ Bl,
                                                 const float* __restrict__ bias,
                                                 float* __restrict__ C, int ldc, int K) {
    extern __shared__ __align__(16) char sm[];
    const int col0 = blockIdx.x << 6;
    const uint32_t smb = smem_u32(sm);
    const int t = threadIdx.x;
    const int w = t >> 5;
    const int row0 = blockIdx.y << 7;
    const int m0 = (w >> 1) << 5, n0 = (w & 1) << 5;
    const int KT = K >> 5;

    auto issue = [&](int kt, int stg) {
        int k0 = kt << 5;
        uint32_t sb = smb + (uint32_t)stg * 30720;
#pragma unroll
        for (int i = 0; i < 2; i++) {
            int id = t + (i << 8);
            int r = id >> 2, k8 = (id & 3) << 3;
            uint32_t so = (uint32_t)(r * 40 + k8) << 1;
            cpa16(sb + so,         Ah + (size_t)(row0 + r) * K + k0 + k8);
            cpa16(sb + 10240 + so, Al + (size_t)(row0 + r) * K + k0 + k8);
        }
        {
            int r = t >> 2, k8 = (t & 3) << 3;
            uint32_t so = (uint32_t)(r * 40 + k8) << 1;
            cpa16(sb + 20480 + so, Bh + (size_t)(col0 + r) * K + k0 + k8);
            cpa16(sb + 25600 + so, Bl + (size_t)(col0 + r) * K + k0 + k8);
        }
        cp_commit();
    };

    wmma::fragment<wmma::accumulator, 16, 16, 16, float> acc[2][2];
#pragma unroll
    for (int mi = 0; mi < 2; mi++)
#pragma unroll
        for (int ni = 0; ni < 2; ni++)
            wmma::fill_fragment(acc[mi][ni], 0.f);

    issue(0, 0);
    issue(1, 1);
    for (int kt = 0; kt < KT; kt++) {
        if (kt + 1 < KT) cp_wait1(); else cp_wait0();
        __syncthreads();
        if (kt + 2 < KT) issue(kt + 2, (kt + 2) % 3);
        char* sb = sm + (kt % 3) * 30720;
        __nv_bfloat16* sAh = (__nv_bfloat16*)sb;
        __nv_bfloat16* sAl = (__nv_bfloat16*)(sb + 10240);
        __nv_bfloat16* sBh = (__nv_bfloat16*)(sb + 20480);
        __nv_bfloat16* sBl = (__nv_bfloat16*)(sb + 25600);
#pragma unroll
        for (int ks = 0; ks < 2; ks++) {
            wmma::fragment<wmma::matrix_a, 16, 16, 16, __nv_bfloat16, wmma::row_major> ah0, ah1, al0, al1;
            wmma::fragment<wmma::matrix_b, 16, 16, 16, __nv_bfloat16, wmma::col_major> bh0, bh1, bl0, bl1;
            wmma::load_matrix_sync(ah0, sAh + (size_t)m0 * 40 + ks * 16, 40);
            wmma::load_matrix_sync(ah1, sAh + (size_t)(m0 + 16) * 40 + ks * 16, 40);
            wmma::load_matrix_sync(al0, sAl + (size_t)m0 * 40 + ks * 16, 40);
            wmma::load_matrix_sync(al1, sAl + (size_t)(m0 + 16) * 40 + ks * 16, 40);
            wmma::load_matrix_sync(bh0, sBh + (size_t)n0 * 40 + ks * 16, 40);
            wmma::load_matrix_sync(bh1, sBh + (size_t)(n0 + 16) * 40 + ks * 16, 40);
            wmma::load_matrix_sync(bl0, sBl + (size_t)n0 * 40 + ks * 16, 40);
            wmma::load_matrix_sync(bl1, sBl + (size_t)(n0 + 16) * 40 + ks * 16, 40);

            wmma::mma_sync(acc[0][0], ah0, bh0, acc[0][0]);
            wmma::mma_sync(acc[0][1], ah0, bh1, acc[0][1]);
            wmma::mma_sync(acc[1][0], ah1, bh0, acc[1][0]);
            wmma::mma_sync(acc[1][1], ah1, bh1, acc[1][1]);
            wmma::mma_sync(acc[0][0], ah0, bl0, acc[0][0]);
            wmma::mma_sync(acc[0][1], ah0, bl1, acc[0][1]);
            wmma::mma_sync(acc[1][0], ah1, bl0, acc[1][0]);
            wmma::mma_sync(acc[1][1], ah1, bl1, acc[1][1]);
            wmma::mma_sync(acc[0][0], al0, bh0, acc[0][0]);
            wmma::mma_sync(acc[0][1], al0, bh1, acc[0][1]);
            wmma::mma_sync(acc[1][0], al1, bh0, acc[1][0]);
            wmma::mma_sync(acc[1][1], al1, bh1, acc[1][1]);
        }
    }
    __syncthreads();

    float* scratch = (float*)sm;
#pragma unroll
    for (int mi = 0; mi < 2; mi++)
#pragma unroll
        for (int ni = 0; ni < 2; ni++)
            wmma::store_matrix_sync(scratch + (size_t)(m0 + mi * 16) * 64 + n0 + ni * 16,
                                    acc[mi][ni], 64, wmma::mem_row_major);
    __syncthreads();

    int r = t >> 1, cc = (t & 1) << 5;
#pragma unroll
    for (int q = 0; q < 8; q++) {
        float4 v = *(float4*)(scratch + r * 64 + cc + q * 4);
        float4 bb = *(const float4*)(bias + col0 + cc + q * 4);
        v.x += bb.x; v.y += bb.y; v.z += bb.z; v.w += bb.w;
        *(float4*)(C + (size_t)(row0 + r) * ldc + col0 + cc + q * 4) = v;
    }
}

// ============================================================================
// conv_out: 3-stage pipelined with transposed NCHW store.
// ============================================================================
#define GTR_SMEM 92160

__global__ __launch_bounds__(256) void bfgemm_tr_bf(const __nv_bfloat16* __restrict__ Ah,
                                                    const __nv_bfloat16* __restrict__ Al,
                                                    const __nv_bfloat16* __restrict__ Bh,
                                                    const __nv_bfloat16* __restrict__ Bl,
                                                    const float* __restrict__ bias,
                                                    float* __restrict__ out, int K) {
    extern __shared__ __align__(16) char sm[];
    const uint32_t smb = smem_u32(sm);
    const int t = threadIdx.x;
    const int w = t >> 5;
    const int row0 = blockIdx.y << 7, col0 = blockIdx.x << 6;
    const int b2 = row0 >> 12, hw0 = row0 & 4095;
    const int m0 = (w >> 1) << 5, n0 = (w & 1) << 5;
    const int KT = K >> 5;

    auto issue = [&](int kt, int stg) {
        int k0 = kt << 5;
        uint32_t sb = smb + (uint32_t)stg * 30720;
#pragma unroll
        for (int i = 0; i < 2; i++) {
            int id = t + (i << 8);
            int r = id >> 2, k8 = (id & 3) << 3;
            uint32_t so = (uint32_t)(r * 40 + k8) << 1;
            cpa16(sb + so,         Ah + (size_t)(row0 + r) * K + k0 + k8);
            cpa16(sb + 10240 + so, Al + (size_t)(row0 + r) * K + k0 + k8);
        }
        {
            int r = t >> 2, k8 = (t & 3) << 3;
            uint32_t so = (uint32_t)(r * 40 + k8) << 1;
            cpa16(sb + 20480 + so, Bh + (size_t)(col0 + r) * K + k0 + k8);
            cpa16(sb + 25600 + so, Bl + (size_t)(col0 + r) * K + k0 + k8);
        }
        cp_commit();
    };

    wmma::fragment<wmma::accumulator, 16, 16, 16, float> acc[2][2];
#pragma unroll
    for (int mi = 0; mi < 2; mi++)
#pragma unroll
        for (int ni = 0; ni < 2; ni++)
            wmma::fill_fragment(acc[mi][ni], 0.f);

    issue(0, 0);
    issue(1, 1);
    for (int kt = 0; kt < KT; kt++) {
        if (kt + 1 < KT) cp_wait1(); else cp_wait0();
        __syncthreads();
        if (kt + 2 < KT) issue(kt + 2, (kt + 2) % 3);
        char* sb = sm + (kt % 3) * 30720;
        __nv_bfloat16* sAh = (__nv_bfloat16*)sb;
        __nv_bfloat16* sAl = (__nv_bfloat16*)(sb + 10240);
        __nv_bfloat16* sBh = (__nv_bfloat16*)(sb + 20480);
        __nv_bfloat16* sBl = (__nv_bfloat16*)(sb + 25600);
#pragma unroll
        for (int ks = 0; ks < 2; ks++) {
            wmma::fragment<wmma::matrix_a, 16, 16, 16, __nv_bfloat16, wmma::row_major> ah0, ah1, al0, al1;
            wmma::fragment<wmma::matrix_b, 16, 16, 16, __nv_bfloat16, wmma::col_major> bh0, bh1, bl0, bl1;
            wmma::load_matrix_sync(ah0, sAh + (size_t)m0 * 40 + ks * 16, 40);
            wmma::load_matrix_sync(ah1, sAh + (size_t)(m0 + 16) * 40 + ks * 16, 40);
            wmma::load_matrix_sync(al0, sAl + (size_t)m0 * 40 + ks * 16, 40);
            wmma::load_matrix_sync(al1, sAl + (size_t)(m0 + 16) * 40 + ks * 16, 40);
            wmma::load_matrix_sync(bh0, sBh + (size_t)n0 * 40 + ks * 16, 40);
            wmma::load_matrix_sync(bh1, sBh + (size_t)(n0 + 16) * 40 + ks * 16, 40);
            wmma::load_matrix_sync(bl0, sBl + (size_t)n0 * 40 + ks * 16, 40);
            wmma::load_matrix_sync(bl1, sBl + (size_t)(n0 + 16) * 40 + ks * 16, 40);

            wmma::mma_sync(acc[0][0], ah0, bh0, acc[0][0]);
            wmma::mma_sync(acc[0][1], ah0, bh1, acc[0][1]);
            wmma::mma_sync(acc[1][0], ah1, bh0, acc[1][0]);
            wmma::mma_sync(acc[1][1], ah1, bh1, acc[1][1]);
            wmma::mma_sync(acc[0][0], ah0, bl0, acc[0][0]);
            wmma::mma_sync(acc[0][1], ah0, bl1, acc[0][1]);
            wmma::mma_sync(acc[1][0], ah1, bl0, acc[1][0]);
            wmma::mma_sync(acc[1][1], ah1, bl1, acc[1][1]);
            wmma::mma_sync(acc[0][0], al0, bh0, acc[0][0]);
            wmma::mma_sync(acc[0][1], al0, bh1, acc[0][1]);
            wmma::mma_sync(acc[1][0], al1, bh0, acc[1][0]);
            wmma::mma_sync(acc[1][1], al1, bh1, acc[1][1]);
        }
    }
    __syncthreads();

    float* scratch = (float*)sm;
#pragma unroll
    for (int mi = 0; mi < 2; mi++)
#pragma unroll
        for (int ni = 0; ni < 2; ni++)
            wmma::store_matrix_sync(scratch + (size_t)(n0 + ni * 16) * 132 + m0 + mi * 16,
                                    acc[mi][ni], 132, wmma::mem_col_major);
    __syncthreads();

    const int lane = t & 31;
#pragma unroll
    for (int nn = 0; nn < 8; nn++) {
        int n = (w << 3) + nn;
        float bv = bias[col0 + n];
        float* orow = out + (size_t)b2 * 1048576 + (size_t)(col0 + n) * 4096 + hw0;
#pragma unroll
        for (int it = 0; it < 4; it++) {
            int m = (it << 5) + lane;
            orow[m] = scratch[n * 132 + m] + bv;
        }
    }
}

// ============================================================================
// Windowed attention, 4-way key-split, LAZY-RESCALE online softmax.
// ============================================================================
#define ATTN_SMEM 52224

__global__ __launch_bounds__(256) void attn_kernel(const float* __restrict__ qkv,
                                                   __nv_bfloat16* __restrict__ Oh,
                                                   __nv_bfloat16* __restrict__ Ol) {
    extern __shared__ __align__(16) char asmem[];
    float4 (*sK)[4] = (float4(*)[4])asmem;
    float4 (*sV)[4] = (float4(*)[4])(asmem + 16384);
    float* pm = (float*)(asmem + 32768);
    float* pl = (float*)(asmem + 33792);
    float* po = (float*)(asmem + 34816);

    const int h = blockIdx.x, w = blockIdx.y;
    const int t = threadIdx.x;
    const int sg = t >> 6, q = t & 63;
    const int T = g_win_cnt[w];
    const int* wt = &g_win_tok[w * CAP];

    for (int j = t; j < T; j += 256) {
        int tok = wt[j];
        const float4* kp = (const float4*)(qkv + (size_t)tok * 384 + 128 + h * 16);
        const float4* vp = (const float4*)(qkv + (size_t)tok * 384 + 256 + h * 16);
        sK[j][0] = kp[0]; sK[j][1] = kp[1]; sK[j][2] = kp[2]; sK[j][3] = kp[3];
        sV[j][0] = vp[0]; sV[j][1] = vp[1]; sV[j][2] = vp[2]; sV[j][3] = vp[3];
    }
    __syncthreads();

    const int qtok = wt[q];
    const float4* qp = (const float4*)(qkv + (size_t)qtok * 384 + h * 16);
    float4 q0 = qp[0], q1 = qp[1], q2 = qp[2], q3 = qp[3];

    const int j0 = (T * sg) >> 2, j1 = (T * (sg + 1)) >> 2;
    float m = -1e30f, l = 0.f;
    float4 o0 = {0,0,0,0}, o1 = {0,0,0,0}, o2 = {0,0,0,0}, o3 = {0,0,0,0};
    for (int j = j0; j < j1; j++) {
        float4 k0 = sK[j][0], k1 = sK[j][1], k2 = sK[j][2], k3 = sK[j][3];
        float s = q0.x*k0.x + q0.y*k0.y + q0.z*k0.z + q0.w*k0.w
                + q1.x*k1.x + q1.y*k1.y + q1.z*k1.z + q1.w*k1.w
                + q2.x*k2.x + q2.y*k2.y + q2.z*k2.z + q2.w*k2.w
                + q3.x*k3.x + q3.y*k3.y + q3.z*k3.z + q3.w*k3.w;
        s *= 0.25f;
        if (s > m) {
            // rare path: rescale accumulator state to new max
            float sc = __expf(m - s);
            l *= sc;
            o0.x *= sc; o0.y *= sc; o0.z *= sc; o0.w *= sc;
            o1.x *= sc; o1.y *= sc; o1.z *= sc; o1.w *= sc;
            o2.x *= sc; o2.y *= sc; o2.z *= sc; o2.w *= sc;
            o3.x *= sc; o3.y *= sc; o3.z *= sc; o3.w *= sc;
            m = s;
        }
        float p = __expf(s - m);
        l += p;
        float4 v0 = sV[j][0], v1 = sV[j][1], v2 = sV[j][2], v3 = sV[j][3];
        o0.x += p*v0.x; o0.y += p*v0.y; o0.z += p*v0.z; o0.w += p*v0.w;
        o1.x += p*v1.x; o1.y += p*v1.y; o1.z += p*v1.z; o1.w += p*v1.w;
        o2.x += p*v2.x; o2.y += p*v2.y; o2.z += p*v2.z; o2.w += p*v2.w;
        o3.x += p*v3.x; o3.y += p*v3.y; o3.z += p*v3.z; o3.w += p*v3.w;
    }
    pm[t] = m;
    pl[t] = l;
    float* pop = po + (sg * 64 + q) * 17;
    pop[0] = o0.x; pop[1] = o0.y; pop[2]  = o0.z; pop[3]  = o0.w;
    pop[4] = o1.x; pop[5] = o1.y; pop[6]  = o1.z; pop[7]  = o1.w;
    pop[8] = o2.x; pop[9] = o2.y; pop[10] = o2.z; pop[11] = o2.w;
    pop[12] = o3.x; pop[13] = o3.y; pop[14] = o3.z; pop[15] = o3.w;
    __syncthreads();

    if (t < 64) {
        float m0 = pm[q], m1 = pm[64 + q], m2 = pm[128 + q], m3 = pm[192 + q];
        float mm = fmaxf(fmaxf(m0, m1), fmaxf(m2, m3));
        float e0 = __expf(m0 - mm), e1 = __expf(m1 - mm);
        float e2 = __expf(m2 - mm), e3 = __expf(m3 - mm);
        float lt = pl[q] * e0 + pl[64 + q] * e1 + pl[128 + q] * e2 + pl[192 + q] * e3;
        float inv = 1.f / lt;
        const float* p0 = po + q * 17;
        const float* p1 = po + (64 + q) * 17;
        const float* p2 = po + (128 + q) * 17;
        const float* p3 = po + (192 + q) * 17;
        uint32_t* oh32 = (uint32_t*)Oh;
        uint32_t* ol32 = (uint32_t*)Ol;
        int ob = qtok * 64 + h * 8;
#pragma unroll
        for (int j = 0; j < 8; j++) {
            float vlo = (p0[2*j]   * e0 + p1[2*j]   * e1 + p2[2*j]   * e2 + p3[2*j]   * e3) * inv;
            float vhi = (p0[2*j+1] * e0 + p1[2*j+1] * e1 + p2[2*j+1] * e2 + p3[2*j+1] * e3) * inv;
            uint32_t hh = bf16x2_of(vhi, vlo);
            oh32[ob + j] = hh;
            ol32[ob + j] = bf16x2_of(vhi - bf16hi_f(hh), vlo - bf16lo_f(hh));
        }
    }
}

// ============================================================================
// Fused proj + RK4 ODE on raw mma.sync — double-buffered Z, 1 sync per eval.
// ============================================================================
#define ODE_SMEM 209408

__global__ __launch_bounds__(256, 1) void ode_mma(const __nv_bfloat16* __restrict__ Oh,
                                                  const __nv_bfloat16* __restrict__ Ol,
                                                  const __nv_bfloat16* __restrict__ PWh,
                                                  const __nv_bfloat16* __restrict__ PWl,
                                                  const float* __restrict__ pbias,
                                                  const __nv_bfloat16* __restrict__ Wh_g,
                                                  const __nv_bfloat16* __restrict__ Wl_g,
                                                  const float* __restrict__ bias,
                                                  __nv_bfloat16* __restrict__ Rh,
                                                  __nv_bfloat16* __restrict__ Rl) {
    extern __shared__ __align__(16) char sm[];
    float* sBias = (float*)sm;
    char* sWh  = sm + 512;
    char* sWl  = sm + 35328;
    char* sZh0 = sm + 70144;
    char* sZl0 = sm + 87552;
    char* sZh1 = sm + 104960;
    char* sZl1 = sm + 122368;
    char* sPWh = sm + 139776;
    char* sPWl = sm + 174592;
    float* sImg = (float*)(sm + 139776);

    const int t = threadIdx.x;
    const int lane = t & 31;
    const int wid = t >> 5;
    const int wm = wid >> 2, wn = wid & 3;
    const int m0 = wm << 5, n0 = wn << 5;
    const int row0 = blockIdx.x << 6;

    {
        const uint32_t* wh32 = (const uint32_t*)Wh_g;
        const uint32_t* wl32 = (const uint32_t*)Wl_g;
        const uint32_t* ph32 = (const uint32_t*)PWh;
        const uint32_t* pl32 = (const uint32_t*)PWl;
        uint32_t* dWh = (uint32_t*)sWh;
        uint32_t* dWl = (uint32_t*)sWl;
        uint32_t* dPh = (uint32_t*)sPWh;
        uint32_t* dPl = (uint32_t*)sPWl;
        for (int idx = t; idx < 8192; idx += 256) {
            int n = idx >> 6, c2 = idx & 63;
            dWh[n * 68 + c2] = wh32[idx];
            dWl[n * 68 + c2] = wl32[idx];
            dPh[n * 68 + c2] = ph32[idx];
            dPl[n * 68 + c2] = pl32[idx];
        }
        const uint32_t* oh32 = (const uint32_t*)Oh + (size_t)row0 * 64;
        const uint32_t* ol32 = (const uint32_t*)Ol + (size_t)row0 * 64;
        uint32_t* zh = (uint32_t*)sZh0;
        uint32_t* zl = (uint32_t*)sZl0;
        for (int idx = t; idx < 4096; idx += 256) {
            int n = idx >> 6, c2 = idx & 63;
            zh[n * 68 + c2] = oh32[idx];
            zl[n * 68 + c2] = ol32[idx];
        }
        if (t < 128) sBias[t] = bias[t];
    }
    __syncthreads();

    const int g3 = lane >> 3, r8 = lane & 7;
    uint32_t aOff[2], bOff[2];
#pragma unroll
    for (int mf = 0; mf < 2; mf++)
        aOff[mf] = (uint32_t)((m0 + mf * 16 + (g3 & 1) * 8 + r8) * 136) * 2 + (g3 >> 1) * 16;
#pragma unroll
    for (int nt = 0; nt < 2; nt++)
        bOff[nt] = (uint32_t)((n0 + nt * 16 + (g3 >> 1) * 8 + r8) * 136) * 2 + (g3 & 1) * 16;

    const uint32_t zhA[2] = { smem_u32(sZh0), smem_u32(sZh1) };
    const uint32_t zlA[2] = { smem_u32(sZl0), smem_u32(sZl1) };
    const uint32_t whB = smem_u32(sWh), wlB = smem_u32(sWl);
    const uint32_t phB = smem_u32(sPWh), plB = smem_u32(sPWl);

    const int gr = lane >> 2, q2 = (lane & 3) << 1;
    float bias2[4][2];
#pragma unroll
    for (int nj = 0; nj < 4; nj++) {
        bias2[nj][0] = sBias[n0 + nj * 8 + q2];
        bias2[nj][1] = sBias[n0 + nj * 8 + q2 + 1];
    }

    float d[2][4][4], y[2][4][4], accv[2][4][4];

#define MMA_PHASE(AH, AL, BH, BL)                                                  \
    _Pragma("unroll")                                                              \
    for (int kk = 0; kk < 8; kk++) {                                               \
        uint32_t ko = kk * 32;                                                     \
        uint32_t ah0[4], ah1[4], al0[4], al1[4];                                   \
        uint32_t bh0[4], bh1[4], bl0[4], bl1[4];                                   \
        ldm4(ah0, (AH) + aOff[0] + ko); ldm4(ah1, (AH) + aOff[1] + ko);            \
        ldm4(al0, (AL) + aOff[0] + ko); ldm4(al1, (AL) + aOff[1] + ko);            \
        ldm4(bh0, (BH) + bOff[0] + ko); ldm4(bh1, (BH) + bOff[1] + ko);            \
        ldm4(bl0, (BL) + bOff[0] + ko); ldm4(bl1, (BL) + bOff[1] + ko);            \
        _Pragma("unroll")                                                          \
        for (int nj = 0; nj < 4; nj++) {                                           \
            const uint32_t* bhp = (nj < 2) ? bh0 : bh1;                            \
            const uint32_t* blp = (nj < 2) ? bl0 : bl1;                            \
            uint32_t bh_0 = bhp[(nj & 1) * 2], bh_1 = bhp[(nj & 1) * 2 + 1];       \
            uint32_t bl_0 = blp[(nj & 1) * 2], bl_1 = blp[(nj & 1) * 2 + 1];       \
            mma16816(d[0][nj], ah0, bh_0, bh_1);                                   \
            mma16816(d[1][nj], ah1, bh_0, bh_1);                                   \
            mma16816(d[0][nj], al0, bh_0, bh_1);                                   \
            mma16816(d[1][nj], al1, bh_0, bh_1);                                   \
            mma16816(d[0][nj], ah0, bl_0, bl_1);                                   \
            mma16816(d[1][nj], ah1, bl_0, bl_1);                                   \
        }                                                                          \
    }

#pragma unroll
    for (int mf = 0; mf < 2; mf++)
#pragma unroll
        for (int nj = 0; nj < 4; nj++)
#pragma unroll
            for (int i = 0; i < 4; i++) d[mf][nj][i] = 0.f;
    MMA_PHASE(zhA[0], zlA[0], phB, plB)
    __syncthreads();

#pragma unroll
    for (int mf = 0; mf < 2; mf++) {
#pragma unroll
        for (int nj = 0; nj < 4; nj++) {
            const int c = n0 + nj * 8 + q2;
            float pb0 = pbias[c], pb1 = pbias[c + 1];
#pragma unroll
            for (int hh = 0; hh < 2; hh++) {
                const int row = m0 + mf * 16 + gr + hh * 8;
                float z0 = d[mf][nj][hh * 2]     + pb0;
                float z1 = d[mf][nj][hh * 2 + 1] + pb1;
                y[mf][nj][hh * 2] = z0; y[mf][nj][hh * 2 + 1] = z1;
                *(float2*)(sImg + row * 128 + c) = make_float2(z0, z1);
                uint32_t hz = bf16x2_of(z1, z0);
                *(uint32_t*)(sZh1 + (row * 136 + c) * 2) = hz;
                *(uint32_t*)(sZl1 + (row * 136 + c) * 2) =
                    bf16x2_of(z1 - bf16hi_f(hz), z0 - bf16lo_f(hz));
            }
        }
    }
    __syncthreads();

    for (int ev = 0; ev < 16; ev++) {
        const int rb = (ev & 1) ^ 1, wb = ev & 1;
#pragma unroll
        for (int mf = 0; mf < 2; mf++)
#pragma unroll
            for (int nj = 0; nj < 4; nj++)
#pragma unroll
                for (int i = 0; i < 4; i++) d[mf][nj][i] = 0.f;
        MMA_PHASE(zhA[rb], zlA[rb], whB, wlB)

        char* zhW = wb ? sZh1 : sZh0;
        char* zlW = wb ? sZl1 : sZl0;
        const int st = ev & 3;
        const float zc = (st < 2) ? 0.125f : 0.25f;
        const float aw = (st == 1 || st == 2) ? 2.f : 1.f;
#pragma unroll
        for (int mf = 0; mf < 2; mf++) {
#pragma unroll
            for (int nj = 0; nj < 4; nj++) {
                const int c = n0 + nj * 8 + q2;
#pragma unroll
                for (int hh = 0; hh < 2; hh++) {
                    const int row = m0 + mf * 16 + gr + hh * 8;
                    float kf0 = fmaxf(d[mf][nj][hh * 2]     + bias2[nj][0], 0.f);
                    float kf1 = fmaxf(d[mf][nj][hh * 2 + 1] + bias2[nj][1], 0.f);
                    float a0 = (st == 0) ? kf0 : accv[mf][nj][hh * 2]     + aw * kf0;
                    float a1 = (st == 0) ? kf1 : accv[mf][nj][hh * 2 + 1] + aw * kf1;
                    accv[mf][nj][hh * 2] = a0; accv[mf][nj][hh * 2 + 1] = a1;
                    float z0, z1;
                    if (st < 3) {
                        z0 = y[mf][nj][hh * 2]     + zc * kf0;
                        z1 = y[mf][nj][hh * 2 + 1] + zc * kf1;
                    } else {
                        y[mf][nj][hh * 2]     += (1.f / 24.f) * a0;
                        y[mf][nj][hh * 2 + 1] += (1.f / 24.f) * a1;
                        z0 = y[mf][nj][hh * 2]; z1 = y[mf][nj][hh * 2 + 1];
                    }
                    uint32_t hz = bf16x2_of(z1, z0);
                    *(uint32_t*)(zhW + (row * 136 + c) * 2) = hz;
                    *(uint32_t*)(zlW + (row * 136 + c) * 2) =
                        bf16x2_of(z1 - bf16hi_f(hz), z0 - bf16lo_f(hz));
                }
            }
        }
        __syncthreads();
    }

    uint32_t* rh32 = (uint32_t*)Rh;
    uint32_t* rl32 = (uint32_t*)Rl;
#pragma unroll
    for (int mf = 0; mf < 2; mf++) {
#pragma unroll
        for (int nj = 0; nj < 4; nj++) {
            const int c = n0 + nj * 8 + q2;
#pragma unroll
            for (int hh = 0; hh < 2; hh++) {
                const int row = m0 + mf * 16 + gr + hh * 8;
                float2 iv = *(const float2*)(sImg + row * 128 + c);
                float r0 = y[mf][nj][hh * 2]     + iv.x;
                float r1 = y[mf][nj][hh * 2 + 1] + iv.y;
                uint32_t hz = bf16x2_of(r1, r0);
                int o = (row0 + row) * 64 + (c >> 1);
                rh32[o] = hz;
                rl32[o] = bf16x2_of(r1 - bf16hi_f(hz), r0 - bf16lo_f(hz));
            }
        }
    }
#undef MMA_PHASE
}

// ---------------- launch ----------------
extern "C" void kernel_launch(void* const* d_in, const int* in_sizes, int n_in,
                              void* d_out, int out_size) {
    const float* img   = (const float*)d_in[0];
    const int*   ptsuv = (const int*)  d_in[1];
    const float* ptsf  = (const float*)d_in[2];
    const float* wci   = (const float*)d_in[3];
    const float* bci   = (const float*)d_in[4];
    const float* wqkv  = (const float*)d_in[5];
    const float* bqkv  = (const float*)d_in[6];
    const float* wpr   = (const float*)d_in[7];
    const float* bpr   = (const float*)d_in[8];
    const float* wode  = (const float*)d_in[9];
    const float* bode  = (const float*)d_in[10];
    const float* wco   = (const float*)d_in[11];
    const float* bco   = (const float*)d_in[12];
    float* out = (float*)d_out;

    float *pqkv;
    __nv_bfloat16 *pwh, *pwl, *pfh, *pfl, *poh, *pol, *prh, *prl, *pih, *pil;
    cudaGetSymbolAddress((void**)&pqkv, g_qkv);
    cudaGetSymbolAddress((void**)&pwh,  g_wh);
    cudaGetSymbolAddress((void**)&pwl,  g_wl);
    cudaGetSymbolAddress((void**)&pfh,  g_feath);
    cudaGetSymbolAddress((void**)&pfl,  g_featl);
    cudaGetSymbolAddress((void**)&poh,  g_oh);
    cudaGetSymbolAddress((void**)&pol,  g_ol);
    cudaGetSymbolAddress((void**)&prh,  g_resh);
    cudaGetSymbolAddress((void**)&prl,  g_resl);
    cudaGetSymbolAddress((void**)&pih,  g_imgh);
    cudaGetSymbolAddress((void**)&pil,  g_imgl);

    cudaFuncSetAttribute(ode_mma,      cudaFuncAttributeMaxDynamicSharedMemorySize, ODE_SMEM);
    cudaFuncSetAttribute(bfgemm_bf,    cudaFuncAttributeMaxDynamicSharedMemorySize, GBF_SMEM);
    cudaFuncSetAttribute(bfgemm_tr_bf, cudaFuncAttributeMaxDynamicSharedMemorySize, GTR_SMEM);
    cudaFuncSetAttribute(mid_kernel,   cudaFuncAttributeMaxDynamicSharedMemorySize, MID_SMEM);
    cudaFuncSetAttribute(attn_kernel,  cudaFuncAttributeMaxDynamicSharedMemorySize, ATTN_SMEM);

    prep<<<3680, 256>>>(wci, wqkv, wpr, wode, wco, ptsf, ptsuv, img);
    // mid: scatter (32) | conv_in (128) | point-KV (256)
    mid_kernel<<<416, 256, MID_SMEM>>>(
        pih, pil, pwh + WOFF_CI, pwl + WOFF_CI, bci, pfh, pfl,
        pfh + (size_t)NPIX * 128, pfl + (size_t)NPIX * 128,
        pwh + WOFF_QKV + 128 * 128, pwl + WOFF_QKV + 128 * 128,
        bqkv + 128, pqkv + (size_t)NPIX * 384 + 128);
    // pixel qkv: M=8192, N=384, K=128
    bfgemm_bf<<<dim3(6, 64), 256, GBF_SMEM>>>(pfh, pfl, pwh + WOFF_QKV, pwl + WOFF_QKV,
                                              bqkv, pqkv, 384, 128);
    // attention (lazy rescale) -> o h/l
    attn_kernel<<<dim3(8, 128), 256, ATTN_SMEM>>>(pqkv, poh, pol);
    // fused proj + RK4 ODE -> res h/l
    ode_mma<<<128, 256, ODE_SMEM>>>(poh, pol, pwh + WOFF_PR, pwl + WOFF_PR, bpr,
                                    pwh + WOFF_ODE, pwl + WOFF_ODE, bode, prh, prl);
    // conv_out -> NCHW out
    bfgemm_tr_bf<<<dim3(4, 64), 256, GTR_SMEM>>>(prh, prl, pwh + WOFF_CO, pwl + WOFF_CO,
                                                 bco, out, 128);
}

// round 16
// speedup vs baseline: 1.0280x; 1.0280x over previous
#include <cuda_runtime.h>
#include <cuda_bf16.h>
#include <mma.h>
#include <cstdint>

using namespace nvcuda;

#define NPIX 8192
#define NPTS 8192
#define NTOK 16384
#define NWIN 128
#define CAP  256
#define NCHUNK 32

// ---------------- scratch (device globals; no allocation) ----------------
__device__ __nv_bfloat16 g_imgh[2097152], g_imgl[2097152];
__device__ __nv_bfloat16 g_feath[NTOK * 128], g_featl[NTOK * 128];
__device__ float g_qkv [NTOK * 384];
__device__ __nv_bfloat16 g_oh[NPIX * 128], g_ol[NPIX * 128];
__device__ __nv_bfloat16 g_resh[NPIX * 128], g_resl[NPIX * 128];
__device__ __nv_bfloat16 g_wh[147456];
__device__ __nv_bfloat16 g_wl[147456];
__device__ int   g_ptw [NPTS];
__device__ int   g_hist[NCHUNK * NWIN];
__device__ int   g_win_tok[NWIN * CAP];
__device__ int   g_win_cnt[NWIN];

#define WOFF_CI  0
#define WOFF_QKV 32768
#define WOFF_PR  81920
#define WOFF_ODE 98304
#define WOFF_CO  114688

// ---------------- helpers ----------------
__device__ __forceinline__ uint32_t bf16x2_of(float hi, float lo) {
    uint32_t r; asm("cvt.rn.bf16x2.f32 %0, %1, %2;" : "=r"(r) : "f"(hi), "f"(lo)); return r;
}
__device__ __forceinline__ float bf16lo_f(uint32_t v) { return __uint_as_float(v << 16); }
__device__ __forceinline__ float bf16hi_f(uint32_t v) { return __uint_as_float(v & 0xffff0000u); }

__device__ __forceinline__ uint32_t smem_u32(const void* p) {
    uint32_t a;
    asm("{ .reg .u64 t; cvta.to.shared.u64 t, %1; cvt.u32.u64 %0, t; }" : "=r"(a) : "l"(p));
    return a;
}
__device__ __forceinline__ void cpa16(uint32_t s, const void* g) {
    asm volatile("cp.async.cg.shared.global [%0], [%1], 16;" :: "r"(s), "l"(g));
}
__device__ __forceinline__ void cp_commit() { asm volatile("cp.async.commit_group;" ::: "memory"); }
__device__ __forceinline__ void cp_wait1() { asm volatile("cp.async.wait_group 1;" ::: "memory"); }
__device__ __forceinline__ void cp_wait0() { asm volatile("cp.async.wait_group 0;" ::: "memory"); }

__device__ __forceinline__ void ldm4(uint32_t* r, uint32_t addr) {
    asm volatile("ldmatrix.sync.aligned.m8n8.x4.shared.b16 {%0,%1,%2,%3}, [%4];"
                 : "=r"(r[0]), "=r"(r[1]), "=r"(r[2]), "=r"(r[3]) : "r"(addr));
}
__device__ __forceinline__ void mma16816(float* d, const uint32_t* a, uint32_t b0, uint32_t b1) {
    asm volatile("mma.sync.aligned.m16n8k16.row.col.f32.bf16.bf16.f32 "
                 "{%0,%1,%2,%3}, {%4,%5,%6,%7}, {%8,%9}, {%0,%1,%2,%3};"
                 : "+f"(d[0]), "+f"(d[1]), "+f"(d[2]), "+f"(d[3])
                 : "r"(a[0]), "r"(a[1]), "r"(a[2]), "r"(a[3]), "r"(b0), "r"(b1));
}

// ============================================================================
// Merged prep: weights | points | wid/hist/pixel slots | image split
// ============================================================================
__global__ void prep(const float* __restrict__ wci, const float* __restrict__ wqkv,
                     const float* __restrict__ wpr, const float* __restrict__ wode,
                     const float* __restrict__ wco, const float* __restrict__ ptsf,
                     const int* __restrict__ uv, const float* __restrict__ img) {
    __shared__ int cnt[NWIN];
    int bid = blockIdx.x, t = threadIdx.x;
    if (bid < 576) {
        int i = bid * 256 + t;
        if (i >= 147456) return;
        float x;
        if (i < WOFF_QKV)      x = wci [i];
        else if (i < WOFF_PR)  x = wqkv[i - WOFF_QKV];
        else if (i < WOFF_ODE) x = wpr [i - WOFF_PR];
        else if (i < WOFF_CO)  x = wode[i - WOFF_ODE];
        else                   x = wco [i - WOFF_CO];
        __nv_bfloat16 h = __float2bfloat16(x);
        g_wh[i] = h;
        g_wl[i] = __float2bfloat16(x - __bfloat162float(h));
    } else if (bid < 1600) {
        int i = (bid - 576) * 256 + t;
        float4 v = ((const float4*)ptsf)[i];
        uint32_t h0 = bf16x2_of(v.y, v.x);
        uint32_t h1 = bf16x2_of(v.w, v.z);
        uint32_t l0 = bf16x2_of(v.y - bf16hi_f(h0), v.x - bf16lo_f(h0));
        uint32_t l1 = bf16x2_of(v.w - bf16hi_f(h1), v.z - bf16lo_f(h1));
        uint32_t* fh = (uint32_t*)g_feath;
        uint32_t* fl = (uint32_t*)g_featl;
        int o = 524288 + 2 * i;
        fh[o] = h0; fh[o + 1] = h1;
        fl[o] = l0; fl[o + 1] = l1;
    } else if (bid < 1632) {
        int c = bid - 1600;
        int i = c * 256 + t;
        if (t < NWIN) cnt[t] = 0;
        __syncthreads();
        int b = uv[3 * i] & 1;
        int u = uv[3 * i + 1] & 63;
        int v = uv[3 * i + 2] & 63;
        int wid = ((b * 8 + (v >> 3)) << 3) + (u >> 3);
        g_ptw[i] = wid;
        atomicAdd(&cnt[wid], 1);
        {
            int w = i >> 6, r = i & 63;
            int wb = w >> 6, wy = (w >> 3) & 7, wx = w & 7;
            int pv = wy * 8 + (r >> 3), pu = wx * 8 + (r & 7);
            g_win_tok[w * CAP + r] = wb * 4096 + pv * 64 + pu;
        }
        __syncthreads();
        if (t < NWIN) g_hist[c * NWIN + t] = cnt[t];
    } else {
        int i = (bid - 1632) * 256 + t;
        float4 v = ((const float4*)img)[i];
        uint32_t h0 = bf16x2_of(v.y, v.x);
        uint32_t h1 = bf16x2_of(v.w, v.z);
        uint32_t l0 = bf16x2_of(v.y - bf16hi_f(h0), v.x - bf16lo_f(h0));
        uint32_t l1 = bf16x2_of(v.w - bf16hi_f(h1), v.z - bf16lo_f(h1));
        uint32_t* ih = (uint32_t*)g_imgh;
        uint32_t* il = (uint32_t*)g_imgl;
        int o = 2 * i;
        ih[o] = h0; ih[o + 1] = h1;
        il[o] = l0; il[o + 1] = l1;
    }
}

// ============================================================================
// MID kernel: scatter | conv_in | point-KV merged (mutually independent).
// ============================================================================
#define MID_SMEM 92160

__global__ __launch_bounds__(256) void mid_kernel(
        const __nv_bfloat16* __restrict__ iAh, const __nv_bfloat16* __restrict__ iAl,
        const __nv_bfloat16* __restrict__ cBh, const __nv_bfloat16* __restrict__ cBl,
        const float* __restrict__ cbias,
        __nv_bfloat16* __restrict__ Ch, __nv_bfloat16* __restrict__ Cl,
        const __nv_bfloat16* __restrict__ pAh, const __nv_bfloat16* __restrict__ pAl,
        const __nv_bfloat16* __restrict__ kBh, const __nv_bfloat16* __restrict__ kBl,
        const float* __restrict__ kbias, float* __restrict__ Ckv) {
    extern __shared__ __align__(16) char sm[];
    const int bid = blockIdx.x;
    const int t = threadIdx.x;

    if (bid < 32) {
        __shared__ int cnt[NWIN];
        int lane = t & 31;
        int c = bid;
        int i = c * 256 + t;
        if (t < NWIN) {
            int run = 0;
            for (int cc = 0; cc < c; cc++) run += g_hist[cc * NWIN + t];
            cnt[t] = run;
            if (c == NCHUNK - 1) {
                int tot = 64 + run + g_hist[(NCHUNK - 1) * NWIN + t];
                g_win_cnt[t] = tot < CAP ? tot : CAP;
            }
        }
        __syncthreads();
        int wid = g_ptw[i];
        for (int wv = 0; wv < 8; wv++) {
            if ((t >> 5) == wv) {
                unsigned mask = __match_any_sync(0xffffffffu, wid);
                int prior = __popc(mask & ((1u << lane) - 1u));
                int base = cnt[wid];
                __syncwarp();
                int rank = 64 + base + prior;
                if (rank < CAP) g_win_tok[wid * CAP + rank] = NPIX + i;
                if (prior == 0) cnt[wid] = base + __popc(mask);
            }
            __syncthreads();
        }
    } else if (bid < 160) {
        const uint32_t smb = smem_u32(sm);
        const int w = t >> 5;
        const int bb = bid - 32;
        const int row0 = (bb >> 1) << 7, col0 = (bb & 1) << 6;
        const int b = row0 >> 12, hw0 = row0 & 4095;
        const int m0 = (w >> 1) << 5, n0 = (w & 1) << 5;
        const int K = 256, KT = 8;

        auto issue = [&](int kt, int stg) {
            int k0 = kt << 5;
            uint32_t sb = smb + (uint32_t)stg * 27648;
#pragma unroll
            for (int i2 = 0; i2 < 2; i2++) {
                int id = t + (i2 << 8);
                int kk = id >> 4, m8 = (id & 15) << 3;
                uint32_t so = (uint32_t)(kk * 136 + m8) << 1;
                size_t g = (size_t)b * 1048576 + (size_t)(k0 + kk) * 4096 + hw0 + m8;
                cpa16(sb + so,        iAh + g);
                cpa16(sb + 8704 + so, iAl + g);
            }
            {
                int r = t >> 2, k8 = (t & 3) << 3;
                uint32_t so = (uint32_t)(r * 40 + k8) << 1;
                cpa16(sb + 17408 + so, cBh + (size_t)(col0 + r) * K + k0 + k8);
                cpa16(sb + 22528 + so, cBl + (size_t)(col0 + r) * K + k0 + k8);
            }
            cp_commit();
        };

        wmma::fragment<wmma::accumulator, 16, 16, 16, float> acc[2][2];
#pragma unroll
        for (int mi = 0; mi < 2; mi++)
#pragma unroll
            for (int ni = 0; ni < 2; ni++)
                wmma::fill_fragment(acc[mi][ni], 0.f);

        issue(0, 0);
        issue(1, 1);
        for (int kt = 0; kt < KT; kt++) {
            if (kt + 1 < KT) cp_wait1(); else cp_wait0();
            __syncthreads();
            if (kt + 2 < KT) issue(kt + 2, (kt + 2) % 3);
            char* sb = sm + (kt % 3) * 27648;
            __nv_bfloat16* sAh = (__nv_bfloat16*)sb;
            __nv_bfloat16* sAl = (__nv_bfloat16*)(sb + 8704);
            __nv_bfloat16* sBh = (__nv_bfloat16*)(sb + 17408);
            __nv_bfloat16* sBl = (__nv_bfloat16*)(sb + 22528);
#pragma unroll
            for (int ks = 0; ks < 2; ks++) {
                wmma::fragment<wmma::matrix_a, 16, 16, 16, __nv_bfloat16, wmma::col_major> ah0, ah1, al0, al1;
                wmma::fragment<wmma::matrix_b, 16, 16, 16, __nv_bfloat16, wmma::col_major> bh0, bh1, bl0, bl1;
                wmma::load_matrix_sync(ah0, sAh + (size_t)ks * 16 * 136 + m0, 136);
                wmma::load_matrix_sync(ah1, sAh + (size_t)ks * 16 * 136 + m0 + 16, 136);
                wmma::load_matrix_sync(al0, sAl + (size_t)ks * 16 * 136 + m0, 136);
                wmma::load_matrix_sync(al1, sAl + (size_t)ks * 16 * 136 + m0 + 16, 136);
                wmma::load_matrix_sync(bh0, sBh + (size_t)n0 * 40 + ks * 16, 40);
                wmma::load_matrix_sync(bh1, sBh + (size_t)(n0 + 16) * 40 + ks * 16, 40);
                wmma::load_matrix_sync(bl0, sBl + (size_t)n0 * 40 + ks * 16, 40);
                wmma::load_matrix_sync(bl1, sBl + (size_t)(n0 + 16) * 40 + ks * 16, 40);

                wmma::mma_sync(acc[0][0], ah0, bh0, acc[0][0]);
                wmma::mma_sync(acc[0][1], ah0, bh1, acc[0][1]);
                wmma::mma_sync(acc[1][0], ah1, bh0, acc[1][0]);
                wmma::mma_sync(acc[1][1], ah1, bh1, acc[1][1]);
                wmma::mma_sync(acc[0][0], ah0, bl0, acc[0][0]);
                wmma::mma_sync(acc[0][1], ah0, bl1, acc[0][1]);
                wmma::mma_sync(acc[1][0], ah1, bl0, acc[1][0]);
                wmma::mma_sync(acc[1][1], ah1, bl1, acc[1][1]);
                wmma::mma_sync(acc[0][0], al0, bh0, acc[0][0]);
                wmma::mma_sync(acc[0][1], al0, bh1, acc[0][1]);
                wmma::mma_sync(acc[1][0], al1, bh0, acc[1][0]);
                wmma::mma_sync(acc[1][1], al1, bh1, acc[1][1]);
            }
        }
        __syncthreads();

        float* scratch = (float*)sm;
#pragma unroll
        for (int mi = 0; mi < 2; mi++)
#pragma unroll
            for (int ni = 0; ni < 2; ni++)
                wmma::store_matrix_sync(scratch + (size_t)(m0 + mi * 16) * 64 + n0 + ni * 16,
                                        acc[mi][ni], 64, wmma::mem_row_major);
        __syncthreads();

        int r = t >> 1, cc = (t & 1) << 5;
        uint32_t* ch32 = (uint32_t*)Ch;
        uint32_t* cl32 = (uint32_t*)Cl;
#pragma unroll
        for (int q = 0; q < 8; q++) {
            float4 v = *(float4*)(scratch + r * 64 + cc + q * 4);
            float4 bb2 = *(const float4*)(cbias + col0 + cc + q * 4);
            v.x += bb2.x; v.y += bb2.y; v.z += bb2.z; v.w += bb2.w;
            uint32_t h01 = bf16x2_of(v.y, v.x);
            uint32_t h23 = bf16x2_of(v.w, v.z);
            uint32_t l01 = bf16x2_of(v.y - bf16hi_f(h01), v.x - bf16lo_f(h01));
            uint32_t l23 = bf16x2_of(v.w - bf16hi_f(h23), v.z - bf16lo_f(h23));
            int o = (row0 + r) * 64 + ((col0 + cc) >> 1) + q * 2;
            ch32[o] = h01; ch32[o + 1] = h23;
            cl32[o] = l01; cl32[o + 1] = l23;
        }
    } else {
        const uint32_t smb = smem_u32(sm);
        const int w = t >> 5;
        const int bb = bid - 160;
        const int row0 = (bb >> 2) << 7, col0 = (bb & 3) << 6;
        const int m0 = (w >> 1) << 5, n0 = (w & 1) << 5;
        const int K = 128, KT = 4, ldc = 384;

        auto issue = [&](int kt, int stg) {
            int k0 = kt << 5;
            uint32_t sb = smb + (uint32_t)stg * 30720;
#pragma unroll
            for (int i2 = 0; i2 < 2; i2++) {
                int id = t + (i2 << 8);
                int r = id >> 2, k8 = (id & 3) << 3;
                uint32_t so = (uint32_t)(r * 40 + k8) << 1;
                cpa16(sb + so,         pAh + (size_t)(row0 + r) * K + k0 + k8);
                cpa16(sb + 10240 + so, pAl + (size_t)(row0 + r) * K + k0 + k8);
            }
            {
                int r = t >> 2, k8 = (t & 3) << 3;
                uint32_t so = (uint32_t)(r * 40 + k8) << 1;
                cpa16(sb + 20480 + so, kBh + (size_t)(col0 + r) * K + k0 + k8);
                cpa16(sb + 25600 + so, kBl + (size_t)(col0 + r) * K + k0 + k8);
            }
            cp_commit();
        };

        wmma::fragment<wmma::accumulator, 16, 16, 16, float> acc[2][2];
#pragma unroll
        for (int mi = 0; mi < 2; mi++)
#pragma unroll
            for (int ni = 0; ni < 2; ni++)
                wmma::fill_fragment(acc[mi][ni], 0.f);

        issue(0, 0);
        issue(1, 1);
        for (int kt = 0; kt < KT; kt++) {
            if (kt + 1 < KT) cp_wait1(); else cp_wait0();
            __syncthreads();
            if (kt + 2 < KT) issue(kt + 2, (kt + 2) % 3);
            char* sb = sm + (kt % 3) * 30720;
            __nv_bfloat16* sAh = (__nv_bfloat16*)sb;
            __nv_bfloat16* sAl = (__nv_bfloat16*)(sb + 10240);
            __nv_bfloat16* sBh = (__nv_bfloat16*)(sb + 20480);
            __nv_bfloat16* sBl = (__nv_bfloat16*)(sb + 25600);
#pragma unroll
            for (int ks = 0; ks < 2; ks++) {
                wmma::fragment<wmma::matrix_a, 16, 16, 16, __nv_bfloat16, wmma::row_major> ah0, ah1, al0, al1;
                wmma::fragment<wmma::matrix_b, 16, 16, 16, __nv_bfloat16, wmma::col_major> bh0, bh1, bl0, bl1;
                wmma::load_matrix_sync(ah0, sAh + (size_t)m0 * 40 + ks * 16, 40);
                wmma::load_matrix_sync(ah1, sAh + (size_t)(m0 + 16) * 40 + ks * 16, 40);
                wmma::load_matrix_sync(al0, sAl + (size_t)m0 * 40 + ks * 16, 40);
                wmma::load_matrix_sync(al1, sAl + (size_t)(m0 + 16) * 40 + ks * 16, 40);
                wmma::load_matrix_sync(bh0, sBh + (size_t)n0 * 40 + ks * 16, 40);
                wmma::load_matrix_sync(bh1, sBh + (size_t)(n0 + 16) * 40 + ks * 16, 40);
                wmma::load_matrix_sync(bl0, sBl + (size_t)n0 * 40 + ks * 16, 40);
                wmma::load_matrix_sync(bl1, sBl + (size_t)(n0 + 16) * 40 + ks * 16, 40);

                wmma::mma_sync(acc[0][0], ah0, bh0, acc[0][0]);
                wmma::mma_sync(acc[0][1], ah0, bh1, acc[0][1]);
                wmma::mma_sync(acc[1][0], ah1, bh0, acc[1][0]);
                wmma::mma_sync(acc[1][1], ah1, bh1, acc[1][1]);
                wmma::mma_sync(acc[0][0], ah0, bl0, acc[0][0]);
                wmma::mma_sync(acc[0][1], ah0, bl1, acc[0][1]);
                wmma::mma_sync(acc[1][0], ah1, bl0, acc[1][0]);
                wmma::mma_sync(acc[1][1], ah1, bl1, acc[1][1]);
                wmma::mma_sync(acc[0][0], al0, bh0, acc[0][0]);
                wmma::mma_sync(acc[0][1], al0, bh1, acc[0][1]);
                wmma::mma_sync(acc[1][0], al1, bh0, acc[1][0]);
                wmma::mma_sync(acc[1][1], al1, bh1, acc[1][1]);
            }
        }
        __syncthreads();

        float* scratch = (float*)sm;
#pragma unroll
        for (int mi = 0; mi < 2; mi++)
#pragma unroll
            for (int ni = 0; ni < 2; ni++)
                wmma::store_matrix_sync(scratch + (size_t)(m0 + mi * 16) * 64 + n0 + ni * 16,
                                        acc[mi][ni], 64, wmma::mem_row_major);
        __syncthreads();

        int r = t >> 1, cc = (t & 1) << 5;
#pragma unroll
        for (int q = 0; q < 8; q++) {
            float4 v = *(float4*)(scratch + r * 64 + cc + q * 4);
            float4 bb2 = *(const float4*)(kbias + col0 + cc + q * 4);
            v.x += bb2.x; v.y += bb2.y; v.z += bb2.z; v.w += bb2.w;
            *(float4*)(Ckv + (size_t)(row0 + r) * ldc + col0 + cc + q * 4) = v;
        }
    }
}

// ============================================================================
// pixel qkv GEMM: 3-stage pipelined, row-major A. Block 128x64.
// ============================================================================
#define GBF_SMEM 92160

__global__ __launch_bounds__(256) void bfgemm_bf(const __nv_bfloat16* __restrict__ Ah,
                                                 const __nv_bfloat16* __restrict__ Al,
                                                 const __nv_bfloat16* __restrict__ Bh,
                                                 const __nv_bfloat16* __restrict__ Bl,
                                                 const float* __restrict__ bias,
                                                 float* __restrict__ C, int ldc, int K) {
    extern __shared__ __align__(16) char sm[];
    const int col0 = blockIdx.x << 6;
    const uint32_t smb = smem_u32(sm);
    const int t = threadIdx.x;
    const int w = t >> 5;
    const int row0 = blockIdx.y << 7;
    const int m0 = (w >> 1) << 5, n0 = (w & 1) << 5;
    const int KT = K >> 5;

    auto issue = [&](int kt, int stg) {
        int k0 = kt << 5;
        uint32_t sb = smb + (uint32_t)stg * 30720;
#pragma unroll
        for (int i = 0; i < 2; i++) {
            int id = t + (i << 8);
            int r = id >> 2, k8 = (id & 3) << 3;
            uint32_t so = (uint32_t)(r * 40 + k8) << 1;
            cpa16(sb + so,         Ah + (size_t)(row0 + r) * K + k0 + k8);
            cpa16(sb + 10240 + so, Al + (size_t)(row0 + r) * K + k0 + k8);
        }
        {
            int r = t >> 2, k8 = (t & 3) << 3;
            uint32_t so = (uint32_t)(r * 40 + k8) << 1;
            cpa16(sb + 20480 + so, Bh + (size_t)(col0 + r) * K + k0 + k8);
            cpa16(sb + 25600 + so, Bl + (size_t)(col0 + r) * K + k0 + k8);
        }
        cp_commit();
    };

    wmma::fragment<wmma::accumulator, 16, 16, 16, float> acc[2][2];
#pragma unroll
    for (int mi = 0; mi < 2; mi++)
#pragma unroll
        for (int ni = 0; ni < 2; ni++)
            wmma::fill_fragment(acc[mi][ni], 0.f);

    issue(0, 0);
    issue(1, 1);
    for (int kt = 0; kt < KT; kt++) {
        if (kt + 1 < KT) cp_wait1(); else cp_wait0();
        __syncthreads();
        if (kt + 2 < KT) issue(kt + 2, (kt + 2) % 3);
        char* sb = sm + (kt % 3) * 30720;
        __nv_bfloat16* sAh = (__nv_bfloat16*)sb;
        __nv_bfloat16* sAl = (__nv_bfloat16*)(sb + 10240);
        __nv_bfloat16* sBh = (__nv_bfloat16*)(sb + 20480);
        __nv_bfloat16* sBl = (__nv_bfloat16*)(sb + 25600);
#pragma unroll
        for (int ks = 0; ks < 2; ks++) {
            wmma::fragment<wmma::matrix_a, 16, 16, 16, __nv_bfloat16, wmma::row_major> ah0, ah1, al0, al1;
            wmma::fragment<wmma::matrix_b, 16, 16, 16, __nv_bfloat16, wmma::col_major> bh0, bh1, bl0, bl1;
            wmma::load_matrix_sync(ah0, sAh + (size_t)m0 * 40 + ks * 16, 40);
            wmma::load_matrix_sync(ah1, sAh + (size_t)(m0 + 16) * 40 + ks * 16, 40);
            wmma::load_matrix_sync(al0, sAl + (size_t)m0 * 40 + ks * 16, 40);
            wmma::load_matrix_sync(al1, sAl + (size_t)(m0 + 16) * 40 + ks * 16, 40);
            wmma::load_matrix_sync(bh0, sBh + (size_t)n0 * 40 + ks * 16, 40);
            wmma::load_matrix_sync(bh1, sBh + (size_t)(n0 + 16) * 40 + ks * 16, 40);
            wmma::load_matrix_sync(bl0, sBl + (size_t)n0 * 40 + ks * 16, 40);
            wmma::load_matrix_sync(bl1, sBl + (size_t)(n0 + 16) * 40 + ks * 16, 40);

            wmma::mma_sync(acc[0][0], ah0, bh0, acc[0][0]);
            wmma::mma_sync(acc[0][1], ah0, bh1, acc[0][1]);
            wmma::mma_sync(acc[1][0], ah1, bh0, acc[1][0]);
            wmma::mma_sync(acc[1][1], ah1, bh1, acc[1][1]);
            wmma::mma_sync(acc[0][0], ah0, bl0, acc[0][0]);
            wmma::mma_sync(acc[0][1], ah0, bl1, acc[0][1]);
            wmma::mma_sync(acc[1][0], ah1, bl0, acc[1][0]);
            wmma::mma_sync(acc[1][1], ah1, bl1, acc[1][1]);
            wmma::mma_sync(acc[0][0], al0, bh0, acc[0][0]);
            wmma::mma_sync(acc[0][1], al0, bh1, acc[0][1]);
            wmma::mma_sync(acc[1][0], al1, bh0, acc[1][0]);
            wmma::mma_sync(acc[1][1], al1, bh1, acc[1][1]);
        }
    }
    __syncthreads();

    float* scratch = (float*)sm;
#pragma unroll
    for (int mi = 0; mi < 2; mi++)
#pragma unroll
        for (int ni = 0; ni < 2; ni++)
            wmma::store_matrix_sync(scratch + (size_t)(m0 + mi * 16) * 64 + n0 + ni * 16,
                                    acc[mi][ni], 64, wmma::mem_row_major);
    __syncthreads();

    int r = t >> 1, cc = (t & 1) << 5;
#pragma unroll
    for (int q = 0; q < 8; q++) {
        float4 v = *(float4*)(scratch + r * 64 + cc + q * 4);
        float4 bb = *(const float4*)(bias + col0 + cc + q * 4);
        v.x += bb.x; v.y += bb.y; v.z += bb.z; v.w += bb.w;
        *(float4*)(C + (size_t)(row0 + r) * ldc + col0 + cc + q * 4) = v;
    }
}

// ============================================================================
// conv_out: 3-stage pipelined with transposed NCHW store.
// ============================================================================
#define GTR_SMEM 92160

__global__ __launch_bounds__(256) void bfgemm_tr_bf(const __nv_bfloat16* __restrict__ Ah,
                                                    const __nv_bfloat16* __restrict__ Al,
                                                    const __nv_bfloat16* __restrict__ Bh,
                                                    const __nv_bfloat16* __restrict__ Bl,
                                                    const float* __restrict__ bias,
                                                    float* __restrict__ out, int K) {
    extern __shared__ __align__(16) char sm[];
    const uint32_t smb = smem_u32(sm);
    const int t = threadIdx.x;
    const int w = t >> 5;
    const int row0 = blockIdx.y << 7, col0 = blockIdx.x << 6;
    const int b2 = row0 >> 12, hw0 = row0 & 4095;
    const int m0 = (w >> 1) << 5, n0 = (w & 1) << 5;
    const int KT = K >> 5;

    auto issue = [&](int kt, int stg) {
        int k0 = kt << 5;
        uint32_t sb = smb + (uint32_t)stg * 30720;
#pragma unroll
        for (int i = 0; i < 2; i++) {
            int id = t + (i << 8);
            int r = id >> 2, k8 = (id & 3) << 3;
            uint32_t so = (uint32_t)(r * 40 + k8) << 1;
            cpa16(sb + so,         Ah + (size_t)(row0 + r) * K + k0 + k8);
            cpa16(sb + 10240 + so, Al + (size_t)(row0 + r) * K + k0 + k8);
        }
        {
            int r = t >> 2, k8 = (t & 3) << 3;
            uint32_t so = (uint32_t)(r * 40 + k8) << 1;
            cpa16(sb + 20480 + so, Bh + (size_t)(col0 + r) * K + k0 + k8);
            cpa16(sb + 25600 + so, Bl + (size_t)(col0 + r) * K + k0 + k8);
        }
        cp_commit();
    };

    wmma::fragment<wmma::accumulator, 16, 16, 16, float> acc[2][2];
#pragma unroll
    for (int mi = 0; mi < 2; mi++)
#pragma unroll
        for (int ni = 0; ni < 2; ni++)
            wmma::fill_fragment(acc[mi][ni], 0.f);

    issue(0, 0);
    issue(1, 1);
    for (int kt = 0; kt < KT; kt++) {
        if (kt + 1 < KT) cp_wait1(); else cp_wait0();
        __syncthreads();
        if (kt + 2 < KT) issue(kt + 2, (kt + 2) % 3);
        char* sb = sm + (kt % 3) * 30720;
        __nv_bfloat16* sAh = (__nv_bfloat16*)sb;
        __nv_bfloat16* sAl = (__nv_bfloat16*)(sb + 10240);
        __nv_bfloat16* sBh = (__nv_bfloat16*)(sb + 20480);
        __nv_bfloat16* sBl = (__nv_bfloat16*)(sb + 25600);
#pragma unroll
        for (int ks = 0; ks < 2; ks++) {
            wmma::fragment<wmma::matrix_a, 16, 16, 16, __nv_bfloat16, wmma::row_major> ah0, ah1, al0, al1;
            wmma::fragment<wmma::matrix_b, 16, 16, 16, __nv_bfloat16, wmma::col_major> bh0, bh1, bl0, bl1;
            wmma::load_matrix_sync(ah0, sAh + (size_t)m0 * 40 + ks * 16, 40);
            wmma::load_matrix_sync(ah1, sAh + (size_t)(m0 + 16) * 40 + ks * 16, 40);
            wmma::load_matrix_sync(al0, sAl + (size_t)m0 * 40 + ks * 16, 40);
            wmma::load_matrix_sync(al1, sAl + (size_t)(m0 + 16) * 40 + ks * 16, 40);
            wmma::load_matrix_sync(bh0, sBh + (size_t)n0 * 40 + ks * 16, 40);
            wmma::load_matrix_sync(bh1, sBh + (size_t)(n0 + 16) * 40 + ks * 16, 40);
            wmma::load_matrix_sync(bl0, sBl + (size_t)n0 * 40 + ks * 16, 40);
            wmma::load_matrix_sync(bl1, sBl + (size_t)(n0 + 16) * 40 + ks * 16, 40);

            wmma::mma_sync(acc[0][0], ah0, bh0, acc[0][0]);
            wmma::mma_sync(acc[0][1], ah0, bh1, acc[0][1]);
            wmma::mma_sync(acc[1][0], ah1, bh0, acc[1][0]);
            wmma::mma_sync(acc[1][1], ah1, bh1, acc[1][1]);
            wmma::mma_sync(acc[0][0], ah0, bl0, acc[0][0]);
            wmma::mma_sync(acc[0][1], ah0, bl1, acc[0][1]);
            wmma::mma_sync(acc[1][0], ah1, bl0, acc[1][0]);
            wmma::mma_sync(acc[1][1], ah1, bl1, acc[1][1]);
            wmma::mma_sync(acc[0][0], al0, bh0, acc[0][0]);
            wmma::mma_sync(acc[0][1], al0, bh1, acc[0][1]);
            wmma::mma_sync(acc[1][0], al1, bh0, acc[1][0]);
            wmma::mma_sync(acc[1][1], al1, bh1, acc[1][1]);
        }
    }
    __syncthreads();

    float* scratch = (float*)sm;
#pragma unroll
    for (int mi = 0; mi < 2; mi++)
#pragma unroll
        for (int ni = 0; ni < 2; ni++)
            wmma::store_matrix_sync(scratch + (size_t)(n0 + ni * 16) * 132 + m0 + mi * 16,
                                    acc[mi][ni], 132, wmma::mem_col_major);
    __syncthreads();

    const int lane = t & 31;
#pragma unroll
    for (int nn = 0; nn < 8; nn++) {
        int n = (w << 3) + nn;
        float bv = bias[col0 + n];
        float* orow = out + (size_t)b2 * 1048576 + (size_t)(col0 + n) * 4096 + hw0;
#pragma unroll
        for (int it = 0; it < 4; it++) {
            int m = (it << 5) + lane;
            orow[m] = scratch[n * 132 + m] + bv;
        }
    }
}

// ============================================================================
// Windowed attention, 4-way key-split, NO-MAX softmax (scores are small;
// exp(s)/sum(exp(s)) computed directly — identical ratio to reference).
// smem: sK 16384 | sV 16384 | pl 1024 | po 4*64*17*4=17408 -> 51200
// ============================================================================
#define ATTN_SMEM 51200

__global__ __launch_bounds__(256) void attn_kernel(const float* __restrict__ qkv,
                                                   __nv_bfloat16* __restrict__ Oh,
                                                   __nv_bfloat16* __restrict__ Ol) {
    extern __shared__ __align__(16) char asmem[];
    float4 (*sK)[4] = (float4(*)[4])asmem;
    float4 (*sV)[4] = (float4(*)[4])(asmem + 16384);
    float* pl = (float*)(asmem + 32768);
    float* po = (float*)(asmem + 33792);

    const int h = blockIdx.x, w = blockIdx.y;
    const int t = threadIdx.x;
    const int sg = t >> 6, q = t & 63;
    const int T = g_win_cnt[w];
    const int* wt = &g_win_tok[w * CAP];

    for (int j = t; j < T; j += 256) {
        int tok = wt[j];
        const float4* kp = (const float4*)(qkv + (size_t)tok * 384 + 128 + h * 16);
        const float4* vp = (const float4*)(qkv + (size_t)tok * 384 + 256 + h * 16);
        sK[j][0] = kp[0]; sK[j][1] = kp[1]; sK[j][2] = kp[2]; sK[j][3] = kp[3];
        sV[j][0] = vp[0]; sV[j][1] = vp[1]; sV[j][2] = vp[2]; sV[j][3] = vp[3];
    }
    __syncthreads();

    const int qtok = wt[q];
    const float4* qp = (const float4*)(qkv + (size_t)qtok * 384 + h * 16);
    float4 q0 = qp[0], q1 = qp[1], q2 = qp[2], q3 = qp[3];

    const int j0 = (T * sg) >> 2, j1 = (T * (sg + 1)) >> 2;
    float l = 0.f;
    float4 o0 = {0,0,0,0}, o1 = {0,0,0,0}, o2 = {0,0,0,0}, o3 = {0,0,0,0};
    for (int j = j0; j < j1; j++) {
        float4 k0 = sK[j][0], k1 = sK[j][1], k2 = sK[j][2], k3 = sK[j][3];
        float s = q0.x*k0.x + q0.y*k0.y + q0.z*k0.z + q0.w*k0.w
                + q1.x*k1.x + q1.y*k1.y + q1.z*k1.z + q1.w*k1.w
                + q2.x*k2.x + q2.y*k2.y + q2.z*k2.z + q2.w*k2.w
                + q3.x*k3.x + q3.y*k3.y + q3.z*k3.z + q3.w*k3.w;
        float p = __expf(s * 0.25f);
        l += p;
        float4 v0 = sV[j][0], v1 = sV[j][1], v2 = sV[j][2], v3 = sV[j][3];
        o0.x += p*v0.x; o0.y += p*v0.y; o0.z += p*v0.z; o0.w += p*v0.w;
        o1.x += p*v1.x; o1.y += p*v1.y; o1.z += p*v1.z; o1.w += p*v1.w;
        o2.x += p*v2.x; o2.y += p*v2.y; o2.z += p*v2.z; o2.w += p*v2.w;
        o3.x += p*v3.x; o3.y += p*v3.y; o3.z += p*v3.z; o3.w += p*v3.w;
    }
    pl[t] = l;
    float* pop = po + (sg * 64 + q) * 17;
    pop[0] = o0.x; pop[1] = o0.y; pop[2]  = o0.z; pop[3]  = o0.w;
    pop[4] = o1.x; pop[5] = o1.y; pop[6]  = o1.z; pop[7]  = o1.w;
    pop[8] = o2.x; pop[9] = o2.y; pop[10] = o2.z; pop[11] = o2.w;
    pop[12] = o3.x; pop[13] = o3.y; pop[14] = o3.z; pop[15] = o3.w;
    __syncthreads();

    if (t < 64) {
        float lt = pl[q] + pl[64 + q] + pl[128 + q] + pl[192 + q];
        float inv = 1.f / lt;
        const float* p0 = po + q * 17;
        const float* p1 = po + (64 + q) * 17;
        const float* p2 = po + (128 + q) * 17;
        const float* p3 = po + (192 + q) * 17;
        uint32_t* oh32 = (uint32_t*)Oh;
        uint32_t* ol32 = (uint32_t*)Ol;
        int ob = qtok * 64 + h * 8;
#pragma unroll
        for (int j = 0; j < 8; j++) {
            float vlo = (p0[2*j]   + p1[2*j]   + p2[2*j]   + p3[2*j])   * inv;
            float vhi = (p0[2*j+1] + p1[2*j+1] + p2[2*j+1] + p3[2*j+1]) * inv;
            uint32_t hh = bf16x2_of(vhi, vlo);
            oh32[ob + j] = hh;
            ol32[ob + j] = bf16x2_of(vhi - bf16hi_f(hh), vlo - bf16lo_f(hh));
        }
    }
}

// ============================================================================
// Fused proj + RK4 ODE on raw mma.sync — double-buffered Z, 1 sync per eval.
// ============================================================================
#define ODE_SMEM 209408

__global__ __launch_bounds__(256, 1) void ode_mma(const __nv_bfloat16* __restrict__ Oh,
                                                  const __nv_bfloat16* __restrict__ Ol,
                                                  const __nv_bfloat16* __restrict__ PWh,
                                                  const __nv_bfloat16* __restrict__ PWl,
                                                  const float* __restrict__ pbias,
                                                  const __nv_bfloat16* __restrict__ Wh_g,
                                                  const __nv_bfloat16* __restrict__ Wl_g,
                                                  const float* __restrict__ bias,
                                                  __nv_bfloat16* __restrict__ Rh,
                                                  __nv_bfloat16* __restrict__ Rl) {
    extern __shared__ __align__(16) char sm[];
    float* sBias = (float*)sm;
    char* sWh  = sm + 512;
    char* sWl  = sm + 35328;
    char* sZh0 = sm + 70144;
    char* sZl0 = sm + 87552;
    char* sZh1 = sm + 104960;
    char* sZl1 = sm + 122368;
    char* sPWh = sm + 139776;
    char* sPWl = sm + 174592;
    float* sImg = (float*)(sm + 139776);

    const int t = threadIdx.x;
    const int lane = t & 31;
    const int wid = t >> 5;
    const int wm = wid >> 2, wn = wid & 3;
    const int m0 = wm << 5, n0 = wn << 5;
    const int row0 = blockIdx.x << 6;

    {
        const uint32_t* wh32 = (const uint32_t*)Wh_g;
        const uint32_t* wl32 = (const uint32_t*)Wl_g;
        const uint32_t* ph32 = (const uint32_t*)PWh;
        const uint32_t* pl32 = (const uint32_t*)PWl;
        uint32_t* dWh = (uint32_t*)sWh;
        uint32_t* dWl = (uint32_t*)sWl;
        uint32_t* dPh = (uint32_t*)sPWh;
        uint32_t* dPl = (uint32_t*)sPWl;
        for (int idx = t; idx < 8192; idx += 256) {
            int n = idx >> 6, c2 = idx & 63;
            dWh[n * 68 + c2] = wh32[idx];
            dWl[n * 68 + c2] = wl32[idx];
            dPh[n * 68 + c2] = ph32[idx];
            dPl[n * 68 + c2] = pl32[idx];
        }
        const uint32_t* oh32 = (const uint32_t*)Oh + (size_t)row0 * 64;
        const uint32_t* ol32 = (const uint32_t*)Ol + (size_t)row0 * 64;
        uint32_t* zh = (uint32_t*)sZh0;
        uint32_t* zl = (uint32_t*)sZl0;
        for (int idx = t; idx < 4096; idx += 256) {
            int n = idx >> 6, c2 = idx & 63;
            zh[n * 68 + c2] = oh32[idx];
            zl[n * 68 + c2] = ol32[idx];
        }
        if (t < 128) sBias[t] = bias[t];
    }
    __syncthreads();

    const int g3 = lane >> 3, r8 = lane & 7;
    uint32_t aOff[2], bOff[2];
#pragma unroll
    for (int mf = 0; mf < 2; mf++)
        aOff[mf] = (uint32_t)((m0 + mf * 16 + (g3 & 1) * 8 + r8) * 136) * 2 + (g3 >> 1) * 16;
#pragma unroll
    for (int nt = 0; nt < 2; nt++)
        bOff[nt] = (uint32_t)((n0 + nt * 16 + (g3 >> 1) * 8 + r8) * 136) * 2 + (g3 & 1) * 16;

    const uint32_t zhA[2] = { smem_u32(sZh0), smem_u32(sZh1) };
    const uint32_t zlA[2] = { smem_u32(sZl0), smem_u32(sZl1) };
    const uint32_t whB = smem_u32(sWh), wlB = smem_u32(sWl);
    const uint32_t phB = smem_u32(sPWh), plB = smem_u32(sPWl);

    const int gr = lane >> 2, q2 = (lane & 3) << 1;
    float bias2[4][2];
#pragma unroll
    for (int nj = 0; nj < 4; nj++) {
        bias2[nj][0] = sBias[n0 + nj * 8 + q2];
        bias2[nj][1] = sBias[n0 + nj * 8 + q2 + 1];
    }

    float d[2][4][4], y[2][4][4], accv[2][4][4];

#define MMA_PHASE(AH, AL, BH, BL)                                                  \
    _Pragma("unroll")                                                              \
    for (int kk = 0; kk < 8; kk++) {                                               \
        uint32_t ko = kk * 32;                                                     \
        uint32_t ah0[4], ah1[4], al0[4], al1[4];                                   \
        uint32_t bh0[4], bh1[4], bl0[4], bl1[4];                                   \
        ldm4(ah0, (AH) + aOff[0] + ko); ldm4(ah1, (AH) + aOff[1] + ko);            \
        ldm4(al0, (AL) + aOff[0] + ko); ldm4(al1, (AL) + aOff[1] + ko);            \
        ldm4(bh0, (BH) + bOff[0] + ko); ldm4(bh1, (BH) + bOff[1] + ko);            \
        ldm4(bl0, (BL) + bOff[0] + ko); ldm4(bl1, (BL) + bOff[1] + ko);            \
        _Pragma("unroll")                                                          \
        for (int nj = 0; nj < 4; nj++) {                                           \
            const uint32_t* bhp = (nj < 2) ? bh0 : bh1;                            \
            const uint32_t* blp = (nj < 2) ? bl0 : bl1;                            \
            uint32_t bh_0 = bhp[(nj & 1) * 2], bh_1 = bhp[(nj & 1) * 2 + 1];       \
            uint32_t bl_0 = blp[(nj & 1) * 2], bl_1 = blp[(nj & 1) * 2 + 1];       \
            mma16816(d[0][nj], ah0, bh_0, bh_1);                                   \
            mma16816(d[1][nj], ah1, bh_0, bh_1);                                   \
            mma16816(d[0][nj], al0, bh_0, bh_1);                                   \
            mma16816(d[1][nj], al1, bh_0, bh_1);                                   \
            mma16816(d[0][nj], ah0, bl_0, bl_1);                                   \
            mma16816(d[1][nj], ah1, bl_0, bl_1);                                   \
        }                                                                          \
    }

#pragma unroll
    for (int mf = 0; mf < 2; mf++)
#pragma unroll
        for (int nj = 0; nj < 4; nj++)
#pragma unroll
            for (int i = 0; i < 4; i++) d[mf][nj][i] = 0.f;
    MMA_PHASE(zhA[0], zlA[0], phB, plB)
    __syncthreads();

#pragma unroll
    for (int mf = 0; mf < 2; mf++) {
#pragma unroll
        for (int nj = 0; nj < 4; nj++) {
            const int c = n0 + nj * 8 + q2;
            float pb0 = pbias[c], pb1 = pbias[c + 1];
#pragma unroll
            for (int hh = 0; hh < 2; hh++) {
                const int row = m0 + mf * 16 + gr + hh * 8;
                float z0 = d[mf][nj][hh * 2]     + pb0;
                float z1 = d[mf][nj][hh * 2 + 1] + pb1;
                y[mf][nj][hh * 2] = z0; y[mf][nj][hh * 2 + 1] = z1;
                *(float2*)(sImg + row * 128 + c) = make_float2(z0, z1);
                uint32_t hz = bf16x2_of(z1, z0);
                *(uint32_t*)(sZh1 + (row * 136 + c) * 2) = hz;
                *(uint32_t*)(sZl1 + (row * 136 + c) * 2) =
                    bf16x2_of(z1 - bf16hi_f(hz), z0 - bf16lo_f(hz));
            }
        }
    }
    __syncthreads();

    for (int ev = 0; ev < 16; ev++) {
        const int rb = (ev & 1) ^ 1, wb = ev & 1;
#pragma unroll
        for (int mf = 0; mf < 2; mf++)
#pragma unroll
            for (int nj = 0; nj < 4; nj++)
#pragma unroll
                for (int i = 0; i < 4; i++) d[mf][nj][i] = 0.f;
        MMA_PHASE(zhA[rb], zlA[rb], whB, wlB)

        char* zhW = wb ? sZh1 : sZh0;
        char* zlW = wb ? sZl1 : sZl0;
        const int st = ev & 3;
        const float zc = (st < 2) ? 0.125f : 0.25f;
        const float aw = (st == 1 || st == 2) ? 2.f : 1.f;
#pragma unroll
        for (int mf = 0; mf < 2; mf++) {
#pragma unroll
            for (int nj = 0; nj < 4; nj++) {
                const int c = n0 + nj * 8 + q2;
#pragma unroll
                for (int hh = 0; hh < 2; hh++) {
                    const int row = m0 + mf * 16 + gr + hh * 8;
                    float kf0 = fmaxf(d[mf][nj][hh * 2]     + bias2[nj][0], 0.f);
                    float kf1 = fmaxf(d[mf][nj][hh * 2 + 1] + bias2[nj][1], 0.f);
                    float a0 = (st == 0) ? kf0 : accv[mf][nj][hh * 2]     + aw * kf0;
                    float a1 = (st == 0) ? kf1 : accv[mf][nj][hh * 2 + 1] + aw * kf1;
                    accv[mf][nj][hh * 2] = a0; accv[mf][nj][hh * 2 + 1] = a1;
                    float z0, z1;
                    if (st < 3) {
                        z0 = y[mf][nj][hh * 2]     + zc * kf0;
                        z1 = y[mf][nj][hh * 2 + 1] + zc * kf1;
                    } else {
                        y[mf][nj][hh * 2]     += (1.f / 24.f) * a0;
                        y[mf][nj][hh * 2 + 1] += (1.f / 24.f) * a1;
                        z0 = y[mf][nj][hh * 2]; z1 = y[mf][nj][hh * 2 + 1];
                    }
                    uint32_t hz = bf16x2_of(z1, z0);
                    *(uint32_t*)(zhW + (row * 136 + c) * 2) = hz;
                    *(uint32_t*)(zlW + (row * 136 + c) * 2) =
                        bf16x2_of(z1 - bf16hi_f(hz), z0 - bf16lo_f(hz));
                }
            }
        }
        __syncthreads();
    }

    uint32_t* rh32 = (uint32_t*)Rh;
    uint32_t* rl32 = (uint32_t*)Rl;
#pragma unroll
    for (int mf = 0; mf < 2; mf++) {
#pragma unroll
        for (int nj = 0; nj < 4; nj++) {
            const int c = n0 + nj * 8 + q2;
#pragma unroll
            for (int hh = 0; hh < 2; hh++) {
                const int row = m0 + mf * 16 + gr + hh * 8;
                float2 iv = *(const float2*)(sImg + row * 128 + c);
                float r0 = y[mf][nj][hh * 2]     + iv.x;
                float r1 = y[mf][nj][hh * 2 + 1] + iv.y;
                uint32_t hz = bf16x2_of(r1, r0);
                int o = (row0 + row) * 64 + (c >> 1);
                rh32[o] = hz;
                rl32[o] = bf16x2_of(r1 - bf16hi_f(hz), r0 - bf16lo_f(hz));
            }
        }
    }
#undef MMA_PHASE
}

// ---------------- launch ----------------
extern "C" void kernel_launch(void* const* d_in, const int* in_sizes, int n_in,
                              void* d_out, int out_size) {
    const float* img   = (const float*)d_in[0];
    const int*   ptsuv = (const int*)  d_in[1];
    const float* ptsf  = (const float*)d_in[2];
    const float* wci   = (const float*)d_in[3];
    const float* bci   = (const float*)d_in[4];
    const float* wqkv  = (const float*)d_in[5];
    const float* bqkv  = (const float*)d_in[6];
    const float* wpr   = (const float*)d_in[7];
    const float* bpr   = (const float*)d_in[8];
    const float* wode  = (const float*)d_in[9];
    const float* bode  = (const float*)d_in[10];
    const float* wco   = (const float*)d_in[11];
    const float* bco   = (const float*)d_in[12];
    float* out = (float*)d_out;

    float *pqkv;
    __nv_bfloat16 *pwh, *pwl, *pfh, *pfl, *poh, *pol, *prh, *prl, *pih, *pil;
    cudaGetSymbolAddress((void**)&pqkv, g_qkv);
    cudaGetSymbolAddress((void**)&pwh,  g_wh);
    cudaGetSymbolAddress((void**)&pwl,  g_wl);
    cudaGetSymbolAddress((void**)&pfh,  g_feath);
    cudaGetSymbolAddress((void**)&pfl,  g_featl);
    cudaGetSymbolAddress((void**)&poh,  g_oh);
    cudaGetSymbolAddress((void**)&pol,  g_ol);
    cudaGetSymbolAddress((void**)&prh,  g_resh);
    cudaGetSymbolAddress((void**)&prl,  g_resl);
    cudaGetSymbolAddress((void**)&pih,  g_imgh);
    cudaGetSymbolAddress((void**)&pil,  g_imgl);

    cudaFuncSetAttribute(ode_mma,      cudaFuncAttributeMaxDynamicSharedMemorySize, ODE_SMEM);
    cudaFuncSetAttribute(bfgemm_bf,    cudaFuncAttributeMaxDynamicSharedMemorySize, GBF_SMEM);
    cudaFuncSetAttribute(bfgemm_tr_bf, cudaFuncAttributeMaxDynamicSharedMemorySize, GTR_SMEM);
    cudaFuncSetAttribute(mid_kernel,   cudaFuncAttributeMaxDynamicSharedMemorySize, MID_SMEM);
    cudaFuncSetAttribute(attn_kernel,  cudaFuncAttributeMaxDynamicSharedMemorySize, ATTN_SMEM);

    prep<<<3680, 256>>>(wci, wqkv, wpr, wode, wco, ptsf, ptsuv, img);
    // mid: scatter (32) | conv_in (128) | point-KV (256)
    mid_kernel<<<416, 256, MID_SMEM>>>(
        pih, pil, pwh + WOFF_CI, pwl + WOFF_CI, bci, pfh, pfl,
        pfh + (size_t)NPIX * 128, pfl + (size_t)NPIX * 128,
        pwh + WOFF_QKV + 128 * 128, pwl + WOFF_QKV + 128 * 128,
        bqkv + 128, pqkv + (size_t)NPIX * 384 + 128);
    // pixel qkv: M=8192, N=384, K=128
    bfgemm_bf<<<dim3(6, 64), 256, GBF_SMEM>>>(pfh, pfl, pwh + WOFF_QKV, pwl + WOFF_QKV,
                                              bqkv, pqkv, 384, 128);
    // attention (no-max softmax) -> o h/l
    attn_kernel<<<dim3(8, 128), 256, ATTN_SMEM>>>(pqkv, poh, pol);
    // fused proj + RK4 ODE -> res h/l
    ode_mma<<<128, 256, ODE_SMEM>>>(poh, pol, pwh + WOFF_PR, pwl + WOFF_PR, bpr,
                                    pwh + WOFF_ODE, pwl + WOFF_ODE, bode, prh, prl);
    // conv_out -> NCHW out
    bfgemm_tr_bf<<<dim3(4, 64), 256, GTR_SMEM>>>(prh, prl, pwh + WOFF_CO, pwl + WOFF_CO,
                                                 bco, out, 128);
}

// round 17
// speedup vs baseline: 1.0304x; 1.0024x over previous
#include <cuda_runtime.h>
#include <cuda_bf16.h>
#include <mma.h>
#include <cstdint>

using namespace nvcuda;
typedef unsigned long long ull;

#define NPIX 8192
#define NPTS 8192
#define NTOK 16384
#define NWIN 128
#define CAP  256
#define NCHUNK 32

// ---------------- scratch (device globals; no allocation) ----------------
__device__ __nv_bfloat16 g_imgh[2097152], g_imgl[2097152];
__device__ __nv_bfloat16 g_feath[NTOK * 128], g_featl[NTOK * 128];
__device__ float g_qkv [NTOK * 384];
__device__ __nv_bfloat16 g_oh[NPIX * 128], g_ol[NPIX * 128];
__device__ __nv_bfloat16 g_resh[NPIX * 128], g_resl[NPIX * 128];
__device__ __nv_bfloat16 g_wh[147456];
__device__ __nv_bfloat16 g_wl[147456];
__device__ int   g_ptw [NPTS];
__device__ int   g_hist[NCHUNK * NWIN];
__device__ int   g_win_tok[NWIN * CAP];
__device__ int   g_win_cnt[NWIN];

#define WOFF_CI  0
#define WOFF_QKV 32768
#define WOFF_PR  81920
#define WOFF_ODE 98304
#define WOFF_CO  114688

// ---------------- helpers ----------------
__device__ __forceinline__ uint32_t bf16x2_of(float hi, float lo) {
    uint32_t r; asm("cvt.rn.bf16x2.f32 %0, %1, %2;" : "=r"(r) : "f"(hi), "f"(lo)); return r;
}
__device__ __forceinline__ float bf16lo_f(uint32_t v) { return __uint_as_float(v << 16); }
__device__ __forceinline__ float bf16hi_f(uint32_t v) { return __uint_as_float(v & 0xffff0000u); }

__device__ __forceinline__ uint32_t smem_u32(const void* p) {
    uint32_t a;
    asm("{ .reg .u64 t; cvta.to.shared.u64 t, %1; cvt.u32.u64 %0, t; }" : "=r"(a) : "l"(p));
    return a;
}
__device__ __forceinline__ void cpa16(uint32_t s, const void* g) {
    asm volatile("cp.async.cg.shared.global [%0], [%1], 16;" :: "r"(s), "l"(g));
}
__device__ __forceinline__ void cp_commit() { asm volatile("cp.async.commit_group;" ::: "memory"); }
__device__ __forceinline__ void cp_wait1() { asm volatile("cp.async.wait_group 1;" ::: "memory"); }
__device__ __forceinline__ void cp_wait0() { asm volatile("cp.async.wait_group 0;" ::: "memory"); }

__device__ __forceinline__ void ldm4(uint32_t* r, uint32_t addr) {
    asm volatile("ldmatrix.sync.aligned.m8n8.x4.shared.b16 {%0,%1,%2,%3}, [%4];"
                 : "=r"(r[0]), "=r"(r[1]), "=r"(r[2]), "=r"(r[3]) : "r"(addr));
}
__device__ __forceinline__ void mma16816(float* d, const uint32_t* a, uint32_t b0, uint32_t b1) {
    asm volatile("mma.sync.aligned.m16n8k16.row.col.f32.bf16.bf16.f32 "
                 "{%0,%1,%2,%3}, {%4,%5,%6,%7}, {%8,%9}, {%0,%1,%2,%3};"
                 : "+f"(d[0]), "+f"(d[1]), "+f"(d[2]), "+f"(d[3])
                 : "r"(a[0]), "r"(a[1]), "r"(a[2]), "r"(a[3]), "r"(b0), "r"(b1));
}

// packed f32x2 helpers (attention inner loop)
__device__ __forceinline__ ull f2fma(ull a, ull b, ull c) {
    ull d; asm("fma.rn.f32x2 %0, %1, %2, %3;" : "=l"(d) : "l"(a), "l"(b), "l"(c)); return d;
}
__device__ __forceinline__ ull pk2(float lo, float hi) {
    ull r; asm("mov.b64 %0, {%1,%2};" : "=l"(r) : "f"(lo), "f"(hi)); return r;
}
__device__ __forceinline__ float2 up2(ull v) {
    float2 f; asm("mov.b64 {%0,%1}, %2;" : "=f"(f.x), "=f"(f.y) : "l"(v)); return f;
}

// ============================================================================
// Merged prep: weights | points | wid/hist/pixel slots | image split
// ============================================================================
__global__ void prep(const float* __restrict__ wci, const float* __restrict__ wqkv,
                     const float* __restrict__ wpr, const float* __restrict__ wode,
                     const float* __restrict__ wco, const float* __restrict__ ptsf,
                     const int* __restrict__ uv, const float* __restrict__ img) {
    __shared__ int cnt[NWIN];
    int bid = blockIdx.x, t = threadIdx.x;
    if (bid < 576) {
        int i = bid * 256 + t;
        if (i >= 147456) return;
        float x;
        if (i < WOFF_QKV)      x = wci [i];
        else if (i < WOFF_PR)  x = wqkv[i - WOFF_QKV];
        else if (i < WOFF_ODE) x = wpr [i - WOFF_PR];
        else if (i < WOFF_CO)  x = wode[i - WOFF_ODE];
        else                   x = wco [i - WOFF_CO];
        __nv_bfloat16 h = __float2bfloat16(x);
        g_wh[i] = h;
        g_wl[i] = __float2bfloat16(x - __bfloat162float(h));
    } else if (bid < 1600) {
        int i = (bid - 576) * 256 + t;
        float4 v = ((const float4*)ptsf)[i];
        uint32_t h0 = bf16x2_of(v.y, v.x);
        uint32_t h1 = bf16x2_of(v.w, v.z);
        uint32_t l0 = bf16x2_of(v.y - bf16hi_f(h0), v.x - bf16lo_f(h0));
        uint32_t l1 = bf16x2_of(v.w - bf16hi_f(h1), v.z - bf16lo_f(h1));
        uint32_t* fh = (uint32_t*)g_feath;
        uint32_t* fl = (uint32_t*)g_featl;
        int o = 524288 + 2 * i;
        fh[o] = h0; fh[o + 1] = h1;
        fl[o] = l0; fl[o + 1] = l1;
    } else if (bid < 1632) {
        int c = bid - 1600;
        int i = c * 256 + t;
        if (t < NWIN) cnt[t] = 0;
        __syncthreads();
        int b = uv[3 * i] & 1;
        int u = uv[3 * i + 1] & 63;
        int v = uv[3 * i + 2] & 63;
        int wid = ((b * 8 + (v >> 3)) << 3) + (u >> 3);
        g_ptw[i] = wid;
        atomicAdd(&cnt[wid], 1);
        {
            int w = i >> 6, r = i & 63;
            int wb = w >> 6, wy = (w >> 3) & 7, wx = w & 7;
            int pv = wy * 8 + (r >> 3), pu = wx * 8 + (r & 7);
            g_win_tok[w * CAP + r] = wb * 4096 + pv * 64 + pu;
        }
        __syncthreads();
        if (t < NWIN) g_hist[c * NWIN + t] = cnt[t];
    } else {
        int i = (bid - 1632) * 256 + t;
        float4 v = ((const float4*)img)[i];
        uint32_t h0 = bf16x2_of(v.y, v.x);
        uint32_t h1 = bf16x2_of(v.w, v.z);
        uint32_t l0 = bf16x2_of(v.y - bf16hi_f(h0), v.x - bf16lo_f(h0));
        uint32_t l1 = bf16x2_of(v.w - bf16hi_f(h1), v.z - bf16lo_f(h1));
        uint32_t* ih = (uint32_t*)g_imgh;
        uint32_t* il = (uint32_t*)g_imgl;
        int o = 2 * i;
        ih[o] = h0; ih[o + 1] = h1;
        il[o] = l0; il[o + 1] = l1;
    }
}

// ============================================================================
// MID kernel: scatter | conv_in | point-KV merged (mutually independent).
// ============================================================================
#define MID_SMEM 92160

__global__ __launch_bounds__(256) void mid_kernel(
        const __nv_bfloat16* __restrict__ iAh, const __nv_bfloat16* __restrict__ iAl,
        const __nv_bfloat16* __restrict__ cBh, const __nv_bfloat16* __restrict__ cBl,
        const float* __restrict__ cbias,
        __nv_bfloat16* __restrict__ Ch, __nv_bfloat16* __restrict__ Cl,
        const __nv_bfloat16* __restrict__ pAh, const __nv_bfloat16* __restrict__ pAl,
        const __nv_bfloat16* __restrict__ kBh, const __nv_bfloat16* __restrict__ kBl,
        const float* __restrict__ kbias, float* __restrict__ Ckv) {
    extern __shared__ __align__(16) char sm[];
    const int bid = blockIdx.x;
    const int t = threadIdx.x;

    if (bid < 32) {
        __shared__ int cnt[NWIN];
        int lane = t & 31;
        int c = bid;
        int i = c * 256 + t;
        if (t < NWIN) {
            int run = 0;
            for (int cc = 0; cc < c; cc++) run += g_hist[cc * NWIN + t];
            cnt[t] = run;
            if (c == NCHUNK - 1) {
                int tot = 64 + run + g_hist[(NCHUNK - 1) * NWIN + t];
                g_win_cnt[t] = tot < CAP ? tot : CAP;
            }
        }
        __syncthreads();
        int wid = g_ptw[i];
        for (int wv = 0; wv < 8; wv++) {
            if ((t >> 5) == wv) {
                unsigned mask = __match_any_sync(0xffffffffu, wid);
                int prior = __popc(mask & ((1u << lane) - 1u));
                int base = cnt[wid];
                __syncwarp();
                int rank = 64 + base + prior;
                if (rank < CAP) g_win_tok[wid * CAP + rank] = NPIX + i;
                if (prior == 0) cnt[wid] = base + __popc(mask);
            }
            __syncthreads();
        }
    } else if (bid < 160) {
        const uint32_t smb = smem_u32(sm);
        const int w = t >> 5;
        const int bb = bid - 32;
        const int row0 = (bb >> 1) << 7, col0 = (bb & 1) << 6;
        const int b = row0 >> 12, hw0 = row0 & 4095;
        const int m0 = (w >> 1) << 5, n0 = (w & 1) << 5;
        const int K = 256, KT = 8;

        auto issue = [&](int kt, int stg) {
            int k0 = kt << 5;
            uint32_t sb = smb + (uint32_t)stg * 27648;
#pragma unroll
            for (int i2 = 0; i2 < 2; i2++) {
                int id = t + (i2 << 8);
                int kk = id >> 4, m8 = (id & 15) << 3;
                uint32_t so = (uint32_t)(kk * 136 + m8) << 1;
                size_t g = (size_t)b * 1048576 + (size_t)(k0 + kk) * 4096 + hw0 + m8;
                cpa16(sb + so,        iAh + g);
                cpa16(sb + 8704 + so, iAl + g);
            }
            {
                int r = t >> 2, k8 = (t & 3) << 3;
                uint32_t so = (uint32_t)(r * 40 + k8) << 1;
                cpa16(sb + 17408 + so, cBh + (size_t)(col0 + r) * K + k0 + k8);
                cpa16(sb + 22528 + so, cBl + (size_t)(col0 + r) * K + k0 + k8);
            }
            cp_commit();
        };

        wmma::fragment<wmma::accumulator, 16, 16, 16, float> acc[2][2];
#pragma unroll
        for (int mi = 0; mi < 2; mi++)
#pragma unroll
            for (int ni = 0; ni < 2; ni++)
                wmma::fill_fragment(acc[mi][ni], 0.f);

        issue(0, 0);
        issue(1, 1);
        for (int kt = 0; kt < KT; kt++) {
            if (kt + 1 < KT) cp_wait1(); else cp_wait0();
            __syncthreads();
            if (kt + 2 < KT) issue(kt + 2, (kt + 2) % 3);
            char* sb = sm + (kt % 3) * 27648;
            __nv_bfloat16* sAh = (__nv_bfloat16*)sb;
            __nv_bfloat16* sAl = (__nv_bfloat16*)(sb + 8704);
            __nv_bfloat16* sBh = (__nv_bfloat16*)(sb + 17408);
            __nv_bfloat16* sBl = (__nv_bfloat16*)(sb + 22528);
#pragma unroll
            for (int ks = 0; ks < 2; ks++) {
                wmma::fragment<wmma::matrix_a, 16, 16, 16, __nv_bfloat16, wmma::col_major> ah0, ah1, al0, al1;
                wmma::fragment<wmma::matrix_b, 16, 16, 16, __nv_bfloat16, wmma::col_major> bh0, bh1, bl0, bl1;
                wmma::load_matrix_sync(ah0, sAh + (size_t)ks * 16 * 136 + m0, 136);
                wmma::load_matrix_sync(ah1, sAh + (size_t)ks * 16 * 136 + m0 + 16, 136);
                wmma::load_matrix_sync(al0, sAl + (size_t)ks * 16 * 136 + m0, 136);
                wmma::load_matrix_sync(al1, sAl + (size_t)ks * 16 * 136 + m0 + 16, 136);
                wmma::load_matrix_sync(bh0, sBh + (size_t)n0 * 40 + ks * 16, 40);
                wmma::load_matrix_sync(bh1, sBh + (size_t)(n0 + 16) * 40 + ks * 16, 40);
                wmma::load_matrix_sync(bl0, sBl + (size_t)n0 * 40 + ks * 16, 40);
                wmma::load_matrix_sync(bl1, sBl + (size_t)(n0 + 16) * 40 + ks * 16, 40);

                wmma::mma_sync(acc[0][0], ah0, bh0, acc[0][0]);
                wmma::mma_sync(acc[0][1], ah0, bh1, acc[0][1]);
                wmma::mma_sync(acc[1][0], ah1, bh0, acc[1][0]);
                wmma::mma_sync(acc[1][1], ah1, bh1, acc[1][1]);
                wmma::mma_sync(acc[0][0], ah0, bl0, acc[0][0]);
                wmma::mma_sync(acc[0][1], ah0, bl1, acc[0][1]);
                wmma::mma_sync(acc[1][0], ah1, bl0, acc[1][0]);
                wmma::mma_sync(acc[1][1], ah1, bl1, acc[1][1]);
                wmma::mma_sync(acc[0][0], al0, bh0, acc[0][0]);
                wmma::mma_sync(acc[0][1], al0, bh1, acc[0][1]);
                wmma::mma_sync(acc[1][0], al1, bh0, acc[1][0]);
                wmma::mma_sync(acc[1][1], al1, bh1, acc[1][1]);
            }
        }
        __syncthreads();

        float* scratch = (float*)sm;
#pragma unroll
        for (int mi = 0; mi < 2; mi++)
#pragma unroll
            for (int ni = 0; ni < 2; ni++)
                wmma::store_matrix_sync(scratch + (size_t)(m0 + mi * 16) * 64 + n0 + ni * 16,
                                        acc[mi][ni], 64, wmma::mem_row_major);
        __syncthreads();

        int r = t >> 1, cc = (t & 1) << 5;
        uint32_t* ch32 = (uint32_t*)Ch;
        uint32_t* cl32 = (uint32_t*)Cl;
#pragma unroll
        for (int q = 0; q < 8; q++) {
            float4 v = *(float4*)(scratch + r * 64 + cc + q * 4);
            float4 bb2 = *(const float4*)(cbias + col0 + cc + q * 4);
            v.x += bb2.x; v.y += bb2.y; v.z += bb2.z; v.w += bb2.w;
            uint32_t h01 = bf16x2_of(v.y, v.x);
            uint32_t h23 = bf16x2_of(v.w, v.z);
            uint32_t l01 = bf16x2_of(v.y - bf16hi_f(h01), v.x - bf16lo_f(h01));
            uint32_t l23 = bf16x2_of(v.w - bf16hi_f(h23), v.z - bf16lo_f(h23));
            int o = (row0 + r) * 64 + ((col0 + cc) >> 1) + q * 2;
            ch32[o] = h01; ch32[o + 1] = h23;
            cl32[o] = l01; cl32[o + 1] = l23;
        }
    } else {
        const uint32_t smb = smem_u32(sm);
        const int w = t >> 5;
        const int bb = bid - 160;
        const int row0 = (bb >> 2) << 7, col0 = (bb & 3) << 6;
        const int m0 = (w >> 1) << 5, n0 = (w & 1) << 5;
        const int K = 128, KT = 4, ldc = 384;

        auto issue = [&](int kt, int stg) {
            int k0 = kt << 5;
            uint32_t sb = smb + (uint32_t)stg * 30720;
#pragma unroll
            for (int i2 = 0; i2 < 2; i2++) {
                int id = t + (i2 << 8);
                int r = id >> 2, k8 = (id & 3) << 3;
                uint32_t so = (uint32_t)(r * 40 + k8) << 1;
                cpa16(sb + so,         pAh + (size_t)(row0 + r) * K + k0 + k8);
                cpa16(sb + 10240 + so, pAl + (size_t)(row0 + r) * K + k0 + k8);
            }
            {
                int r = t >> 2, k8 = (t & 3) << 3;
                uint32_t so = (uint32_t)(r * 40 + k8) << 1;
                cpa16(sb + 20480 + so, kBh + (size_t)(col0 + r) * K + k0 + k8);
                cpa16(sb + 25600 + so, kBl + (size_t)(col0 + r) * K + k0 + k8);
            }
            cp_commit();
        };

        wmma::fragment<wmma::accumulator, 16, 16, 16, float> acc[2][2];
#pragma unroll
        for (int mi = 0; mi < 2; mi++)
#pragma unroll
            for (int ni = 0; ni < 2; ni++)
                wmma::fill_fragment(acc[mi][ni], 0.f);

        issue(0, 0);
        issue(1, 1);
        for (int kt = 0; kt < KT; kt++) {
            if (kt + 1 < KT) cp_wait1(); else cp_wait0();
            __syncthreads();
            if (kt + 2 < KT) issue(kt + 2, (kt + 2) % 3);
            char* sb = sm + (kt % 3) * 30720;
            __nv_bfloat16* sAh = (__nv_bfloat16*)sb;
            __nv_bfloat16* sAl = (__nv_bfloat16*)(sb + 10240);
            __nv_bfloat16* sBh = (__nv_bfloat16*)(sb + 20480);
            __nv_bfloat16* sBl = (__nv_bfloat16*)(sb + 25600);
#pragma unroll
            for (int ks = 0; ks < 2; ks++) {
                wmma::fragment<wmma::matrix_a, 16, 16, 16, __nv_bfloat16, wmma::row_major> ah0, ah1, al0, al1;
                wmma::fragment<wmma::matrix_b, 16, 16, 16, __nv_bfloat16, wmma::col_major> bh0, bh1, bl0, bl1;
                wmma::load_matrix_sync(ah0, sAh + (size_t)m0 * 40 + ks * 16, 40);
                wmma::load_matrix_sync(ah1, sAh + (size_t)(m0 + 16) * 40 + ks * 16, 40);
                wmma::load_matrix_sync(al0, sAl + (size_t)m0 * 40 + ks * 16, 40);
                wmma::load_matrix_sync(al1, sAl + (size_t)(m0 + 16) * 40 + ks * 16, 40);
                wmma::load_matrix_sync(bh0, sBh + (size_t)n0 * 40 + ks * 16, 40);
                wmma::load_matrix_sync(bh1, sBh + (size_t)(n0 + 16) * 40 + ks * 16, 40);
                wmma::load_matrix_sync(bl0, sBl + (size_t)n0 * 40 + ks * 16, 40);
                wmma::load_matrix_sync(bl1, sBl + (size_t)(n0 + 16) * 40 + ks * 16, 40);

                wmma::mma_sync(acc[0][0], ah0, bh0, acc[0][0]);
                wmma::mma_sync(acc[0][1], ah0, bh1, acc[0][1]);
                wmma::mma_sync(acc[1][0], ah1, bh0, acc[1][0]);
                wmma::mma_sync(acc[1][1], ah1, bh1, acc[1][1]);
                wmma::mma_sync(acc[0][0], ah0, bl0, acc[0][0]);
                wmma::mma_sync(acc[0][1], ah0, bl1, acc[0][1]);
                wmma::mma_sync(acc[1][0], ah1, bl0, acc[1][0]);
                wmma::mma_sync(acc[1][1], ah1, bl1, acc[1][1]);
                wmma::mma_sync(acc[0][0], al0, bh0, acc[0][0]);
                wmma::mma_sync(acc[0][1], al0, bh1, acc[0][1]);
                wmma::mma_sync(acc[1][0], al1, bh0, acc[1][0]);
                wmma::mma_sync(acc[1][1], al1, bh1, acc[1][1]);
            }
        }
        __syncthreads();

        float* scratch = (float*)sm;
#pragma unroll
        for (int mi = 0; mi < 2; mi++)
#pragma unroll
            for (int ni = 0; ni < 2; ni++)
                wmma::store_matrix_sync(scratch + (size_t)(m0 + mi * 16) * 64 + n0 + ni * 16,
                                        acc[mi][ni], 64, wmma::mem_row_major);
        __syncthreads();

        int r = t >> 1, cc = (t & 1) << 5;
#pragma unroll
        for (int q = 0; q < 8; q++) {
            float4 v = *(float4*)(scratch + r * 64 + cc + q * 4);
            float4 bb2 = *(const float4*)(kbias + col0 + cc + q * 4);
            v.x += bb2.x; v.y += bb2.y; v.z += bb2.z; v.w += bb2.w;
            *(float4*)(Ckv + (size_t)(row0 + r) * ldc + col0 + cc + q * 4) = v;
        }
    }
}

// ============================================================================
// pixel qkv GEMM: 3-stage pipelined, row-major A. Block 128x64.
// ============================================================================
#define GBF_SMEM 92160

__global__ __launch_bounds__(256) void bfgemm_bf(const __nv_bfloat16* __restrict__ Ah,
                                                 const __nv_bfloat16* __restrict__ Al,
                                                 const __nv_bfloat16* __restrict__ Bh,
                                                 const __nv_bfloat16* __restrict__ Bl,
                                                 const float* __restrict__ bias,
                                                 float* __restrict__ C, int ldc, int K) {
    extern __shared__ __align__(16) char sm[];
    const int col0 = blockIdx.x << 6;
    const uint32_t smb = smem_u32(sm);
    const int t = threadIdx.x;
    const int w = t >> 5;
    const int row0 = blockIdx.y << 7;
    const int m0 = (w >> 1) << 5, n0 = (w & 1) << 5;
    const int KT = K >> 5;

    auto issue = [&](int kt, int stg) {
        int k0 = kt << 5;
        uint32_t sb = smb + (uint32_t)stg * 30720;
#pragma unroll
        for (int i = 0; i < 2; i++) {
            int id = t + (i << 8);
            int r = id >> 2, k8 = (id & 3) << 3;
            uint32_t so = (uint32_t)(r * 40 + k8) << 1;
            cpa16(sb + so,         Ah + (size_t)(row0 + r) * K + k0 + k8);
            cpa16(sb + 10240 + so, Al + (size_t)(row0 + r) * K + k0 + k8);
        }
        {
            int r = t >> 2, k8 = (t & 3) << 3;
            uint32_t so = (uint32_t)(r * 40 + k8) << 1;
            cpa16(sb + 20480 + so, Bh + (size_t)(col0 + r) * K + k0 + k8);
            cpa16(sb + 25600 + so, Bl + (size_t)(col0 + r) * K + k0 + k8);
        }
        cp_commit();
    };

    wmma::fragment<wmma::accumulator, 16, 16, 16, float> acc[2][2];
#pragma unroll
    for (int mi = 0; mi < 2; mi++)
#pragma unroll
        for (int ni = 0; ni < 2; ni++)
            wmma::fill_fragment(acc[mi][ni], 0.f);

    issue(0, 0);
    issue(1, 1);
    for (int kt = 0; kt < KT; kt++) {
        if (kt + 1 < KT) cp_wait1(); else cp_wait0();
        __syncthreads();
        if (kt + 2 < KT) issue(kt + 2, (kt + 2) % 3);
        char* sb = sm + (kt % 3) * 30720;
        __nv_bfloat16* sAh = (__nv_bfloat16*)sb;
        __nv_bfloat16* sAl = (__nv_bfloat16*)(sb + 10240);
        __nv_bfloat16* sBh = (__nv_bfloat16*)(sb + 20480);
        __nv_bfloat16* sBl = (__nv_bfloat16*)(sb + 25600);
#pragma unroll
        for (int ks = 0; ks < 2; ks++) {
            wmma::fragment<wmma::matrix_a, 16, 16, 16, __nv_bfloat16, wmma::row_major> ah0, ah1, al0, al1;
            wmma::fragment<wmma::matrix_b, 16, 16, 16, __nv_bfloat16, wmma::col_major> bh0, bh1, bl0, bl1;
            wmma::load_matrix_sync(ah0, sAh + (size_t)m0 * 40 + ks * 16, 40);
            wmma::load_matrix_sync(ah1, sAh + (size_t)(m0 + 16) * 40 + ks * 16, 40);
            wmma::load_matrix_sync(al0, sAl + (size_t)m0 * 40 + ks * 16, 40);
            wmma::load_matrix_sync(al1, sAl + (size_t)(m0 + 16) * 40 + ks * 16, 40);
            wmma::load_matrix_sync(bh0, sBh + (size_t)n0 * 40 + ks * 16, 40);
            wmma::load_matrix_sync(bh1, sBh + (size_t)(n0 + 16) * 40 + ks * 16, 40);
            wmma::load_matrix_sync(bl0, sBl + (size_t)n0 * 40 + ks * 16, 40);
            wmma::load_matrix_sync(bl1, sBl + (size_t)(n0 + 16) * 40 + ks * 16, 40);

            wmma::mma_sync(acc[0][0], ah0, bh0, acc[0][0]);
            wmma::mma_sync(acc[0][1], ah0, bh1, acc[0][1]);
            wmma::mma_sync(acc[1][0], ah1, bh0, acc[1][0]);
            wmma::mma_sync(acc[1][1], ah1, bh1, acc[1][1]);
            wmma::mma_sync(acc[0][0], ah0, bl0, acc[0][0]);
            wmma::mma_sync(acc[0][1], ah0, bl1, acc[0][1]);
            wmma::mma_sync(acc[1][0], ah1, bl0, acc[1][0]);
            wmma::mma_sync(acc[1][1], ah1, bl1, acc[1][1]);
            wmma::mma_sync(acc[0][0], al0, bh0, acc[0][0]);
            wmma::mma_sync(acc[0][1], al0, bh1, acc[0][1]);
            wmma::mma_sync(acc[1][0], al1, bh0, acc[1][0]);
            wmma::mma_sync(acc[1][1], al1, bh1, acc[1][1]);
        }
    }
    __syncthreads();

    float* scratch = (float*)sm;
#pragma unroll
    for (int mi = 0; mi < 2; mi++)
#pragma unroll
        for (int ni = 0; ni < 2; ni++)
            wmma::store_matrix_sync(scratch + (size_t)(m0 + mi * 16) * 64 + n0 + ni * 16,
                                    acc[mi][ni], 64, wmma::mem_row_major);
    __syncthreads();

    int r = t >> 1, cc = (t & 1) << 5;
#pragma unroll
    for (int q = 0; q < 8; q++) {
        float4 v = *(float4*)(scratch + r * 64 + cc + q * 4);
        float4 bb = *(const float4*)(bias + col0 + cc + q * 4);
        v.x += bb.x; v.y += bb.y; v.z += bb.z; v.w += bb.w;
        *(float4*)(C + (size_t)(row0 + r) * ldc + col0 + cc + q * 4) = v;
    }
}

// ============================================================================
// conv_out: 3-stage pipelined with transposed NCHW store.
// ============================================================================
#define GTR_SMEM 92160

__global__ __launch_bounds__(256) void bfgemm_tr_bf(const __nv_bfloat16* __restrict__ Ah,
                                                    const __nv_bfloat16* __restrict__ Al,
                                                    const __nv_bfloat16* __restrict__ Bh,
                                                    const __nv_bfloat16* __restrict__ Bl,
                                                    const float* __restrict__ bias,
                                                    float* __restrict__ out, int K) {
    extern __shared__ __align__(16) char sm[];
    const uint32_t smb = smem_u32(sm);
    const int t = threadIdx.x;
    const int w = t >> 5;
    const int row0 = blockIdx.y << 7, col0 = blockIdx.x << 6;
    const int b2 = row0 >> 12, hw0 = row0 & 4095;
    const int m0 = (w >> 1) << 5, n0 = (w & 1) << 5;
    const int KT = K >> 5;

    auto issue = [&](int kt, int stg) {
        int k0 = kt << 5;
        uint32_t sb = smb + (uint32_t)stg * 30720;
#pragma unroll
        for (int i = 0; i < 2; i++) {
            int id = t + (i << 8);
            int r = id >> 2, k8 = (id & 3) << 3;
            uint32_t so = (uint32_t)(r * 40 + k8) << 1;
            cpa16(sb + so,         Ah + (size_t)(row0 + r) * K + k0 + k8);
            cpa16(sb + 10240 + so, Al + (size_t)(row0 + r) * K + k0 + k8);
        }
        {
            int r = t >> 2, k8 = (t & 3) << 3;
            uint32_t so = (uint32_t)(r * 40 + k8) << 1;
            cpa16(sb + 20480 + so, Bh + (size_t)(col0 + r) * K + k0 + k8);
            cpa16(sb + 25600 + so, Bl + (size_t)(col0 + r) * K + k0 + k8);
        }
        cp_commit();
    };

    wmma::fragment<wmma::accumulator, 16, 16, 16, float> acc[2][2];
#pragma unroll
    for (int mi = 0; mi < 2; mi++)
#pragma unroll
        for (int ni = 0; ni < 2; ni++)
            wmma::fill_fragment(acc[mi][ni], 0.f);

    issue(0, 0);
    issue(1, 1);
    for (int kt = 0; kt < KT; kt++) {
        if (kt + 1 < KT) cp_wait1(); else cp_wait0();
        __syncthreads();
        if (kt + 2 < KT) issue(kt + 2, (kt + 2) % 3);
        char* sb = sm + (kt % 3) * 30720;
        __nv_bfloat16* sAh = (__nv_bfloat16*)sb;
        __nv_bfloat16* sAl = (__nv_bfloat16*)(sb + 10240);
        __nv_bfloat16* sBh = (__nv_bfloat16*)(sb + 20480);
        __nv_bfloat16* sBl = (__nv_bfloat16*)(sb + 25600);
#pragma unroll
        for (int ks = 0; ks < 2; ks++) {
            wmma::fragment<wmma::matrix_a, 16, 16, 16, __nv_bfloat16, wmma::row_major> ah0, ah1, al0, al1;
            wmma::fragment<wmma::matrix_b, 16, 16, 16, __nv_bfloat16, wmma::col_major> bh0, bh1, bl0, bl1;
            wmma::load_matrix_sync(ah0, sAh + (size_t)m0 * 40 + ks * 16, 40);
            wmma::load_matrix_sync(ah1, sAh + (size_t)(m0 + 16) * 40 + ks * 16, 40);
            wmma::load_matrix_sync(al0, sAl + (size_t)m0 * 40 + ks * 16, 40);
            wmma::load_matrix_sync(al1, sAl + (size_t)(m0 + 16) * 40 + ks * 16, 40);
            wmma::load_matrix_sync(bh0, sBh + (size_t)n0 * 40 + ks * 16, 40);
            wmma::load_matrix_sync(bh1, sBh + (size_t)(n0 + 16) * 40 + ks * 16, 40);
            wmma::load_matrix_sync(bl0, sBl + (size_t)n0 * 40 + ks * 16, 40);
            wmma::load_matrix_sync(bl1, sBl + (size_t)(n0 + 16) * 40 + ks * 16, 40);

            wmma::mma_sync(acc[0][0], ah0, bh0, acc[0][0]);
            wmma::mma_sync(acc[0][1], ah0, bh1, acc[0][1]);
            wmma::mma_sync(acc[1][0], ah1, bh0, acc[1][0]);
            wmma::mma_sync(acc[1][1], ah1, bh1, acc[1][1]);
            wmma::mma_sync(acc[0][0], ah0, bl0, acc[0][0]);
            wmma::mma_sync(acc[0][1], ah0, bl1, acc[0][1]);
            wmma::mma_sync(acc[1][0], ah1, bl0, acc[1][0]);
            wmma::mma_sync(acc[1][1], ah1, bl1, acc[1][1]);
            wmma::mma_sync(acc[0][0], al0, bh0, acc[0][0]);
            wmma::mma_sync(acc[0][1], al0, bh1, acc[0][1]);
            wmma::mma_sync(acc[1][0], al1, bh0, acc[1][0]);
            wmma::mma_sync(acc[1][1], al1, bh1, acc[1][1]);
        }
    }
    __syncthreads();

    float* scratch = (float*)sm;
#pragma unroll
    for (int mi = 0; mi < 2; mi++)
#pragma unroll
        for (int ni = 0; ni < 2; ni++)
            wmma::store_matrix_sync(scratch + (size_t)(n0 + ni * 16) * 132 + m0 + mi * 16,
                                    acc[mi][ni], 132, wmma::mem_col_major);
    __syncthreads();

    const int lane = t & 31;
#pragma unroll
    for (int nn = 0; nn < 8; nn++) {
        int n = (w << 3) + nn;
        float bv = bias[col0 + n];
        float* orow = out + (size_t)b2 * 1048576 + (size_t)(col0 + n) * 4096 + hw0;
#pragma unroll
        for (int it = 0; it < 4; it++) {
            int m = (it << 5) + lane;
            orow[m] = scratch[n * 132 + m] + bv;
        }
    }
}

// ============================================================================
// Windowed attention, 4-way key-split, NO-MAX softmax, packed f32x2 math.
// smem: sK 16384 | sV 16384 | pl 1024 | po 4*64*17*4=17408 -> 51200
// ============================================================================
#define ATTN_SMEM 51200

__global__ __launch_bounds__(256) void attn_kernel(const float* __restrict__ qkv,
                                                   __nv_bfloat16* __restrict__ Oh,
                                                   __nv_bfloat16* __restrict__ Ol) {
    extern __shared__ __align__(16) char asmem[];
    float4 (*sK)[4] = (float4(*)[4])asmem;
    float4 (*sV)[4] = (float4(*)[4])(asmem + 16384);
    float* pl = (float*)(asmem + 32768);
    float* po = (float*)(asmem + 33792);

    const int h = blockIdx.x, w = blockIdx.y;
    const int t = threadIdx.x;
    const int sg = t >> 6, q = t & 63;
    const int T = g_win_cnt[w];
    const int* wt = &g_win_tok[w * CAP];

    for (int j = t; j < T; j += 256) {
        int tok = wt[j];
        const float4* kp = (const float4*)(qkv + (size_t)tok * 384 + 128 + h * 16);
        const float4* vp = (const float4*)(qkv + (size_t)tok * 384 + 256 + h * 16);
        sK[j][0] = kp[0]; sK[j][1] = kp[1]; sK[j][2] = kp[2]; sK[j][3] = kp[3];
        sV[j][0] = vp[0]; sV[j][1] = vp[1]; sV[j][2] = vp[2]; sV[j][3] = vp[3];
    }
    __syncthreads();

    const int qtok = wt[q];
    // q packed into 8 f32x2 registers
    const ulonglong2* qp2 = (const ulonglong2*)(qkv + (size_t)qtok * 384 + h * 16);
    ull q2[8];
#pragma unroll
    for (int i = 0; i < 4; i++) {
        ulonglong2 v = qp2[i];
        q2[2*i] = v.x; q2[2*i + 1] = v.y;
    }

    const int j0 = (T * sg) >> 2, j1 = (T * (sg + 1)) >> 2;
    float l = 0.f;
    ull o2[8];
#pragma unroll
    for (int i = 0; i < 8; i++) o2[i] = 0ull;

    for (int j = j0; j < j1; j++) {
        const ulonglong2* kp2 = (const ulonglong2*)&sK[j][0];
        ulonglong2 ka = kp2[0], kb = kp2[1], kc = kp2[2], kd = kp2[3];
        // dual-chain packed dot
        ull a0 = 0ull, a1 = 0ull;
        a0 = f2fma(q2[0], ka.x, a0); a1 = f2fma(q2[1], ka.y, a1);
        a0 = f2fma(q2[2], kb.x, a0); a1 = f2fma(q2[3], kb.y, a1);
        a0 = f2fma(q2[4], kc.x, a0); a1 = f2fma(q2[5], kc.y, a1);
        a0 = f2fma(q2[6], kd.x, a0); a1 = f2fma(q2[7], kd.y, a1);
        float2 s0 = up2(a0), s1 = up2(a1);
        float s = (s0.x + s0.y) + (s1.x + s1.y);
        float p = __expf(s * 0.25f);
        l += p;
        ull pp = pk2(p, p);
        const ulonglong2* vp2 = (const ulonglong2*)&sV[j][0];
        ulonglong2 va = vp2[0], vb = vp2[1], vc = vp2[2], vd = vp2[3];
        o2[0] = f2fma(pp, va.x, o2[0]); o2[1] = f2fma(pp, va.y, o2[1]);
        o2[2] = f2fma(pp, vb.x, o2[2]); o2[3] = f2fma(pp, vb.y, o2[3]);
        o2[4] = f2fma(pp, vc.x, o2[4]); o2[5] = f2fma(pp, vc.y, o2[5]);
        o2[6] = f2fma(pp, vd.x, o2[6]); o2[7] = f2fma(pp, vd.y, o2[7]);
    }
    pl[t] = l;
    float* pop = po + (sg * 64 + q) * 17;
#pragma unroll
    for (int i = 0; i < 8; i++) {
        float2 ov = up2(o2[i]);
        pop[2*i] = ov.x; pop[2*i + 1] = ov.y;
    }
    __syncthreads();

    if (t < 64) {
        float lt = pl[q] + pl[64 + q] + pl[128 + q] + pl[192 + q];
        float inv = 1.f / lt;
        const float* p0 = po + q * 17;
        const float* p1 = po + (64 + q) * 17;
        const float* p2 = po + (128 + q) * 17;
        const float* p3 = po + (192 + q) * 17;
        uint32_t* oh32 = (uint32_t*)Oh;
        uint32_t* ol32 = (uint32_t*)Ol;
        int ob = qtok * 64 + h * 8;
#pragma unroll
        for (int j = 0; j < 8; j++) {
            float vlo = (p0[2*j]   + p1[2*j]   + p2[2*j]   + p3[2*j])   * inv;
            float vhi = (p0[2*j+1] + p1[2*j+1] + p2[2*j+1] + p3[2*j+1]) * inv;
            uint32_t hh = bf16x2_of(vhi, vlo);
            oh32[ob + j] = hh;
            ol32[ob + j] = bf16x2_of(vhi - bf16hi_f(hh), vlo - bf16lo_f(hh));
        }
    }
}

// ============================================================================
// Fused proj + RK4 ODE on raw mma.sync — double-buffered Z, 1 sync per eval.
// ============================================================================
#define ODE_SMEM 209408

__global__ __launch_bounds__(256, 1) void ode_mma(const __nv_bfloat16* __restrict__ Oh,
                                                  const __nv_bfloat16* __restrict__ Ol,
                                                  const __nv_bfloat16* __restrict__ PWh,
                                                  const __nv_bfloat16* __restrict__ PWl,
                                                  const float* __restrict__ pbias,
                                                  const __nv_bfloat16* __restrict__ Wh_g,
                                                  const __nv_bfloat16* __restrict__ Wl_g,
                                                  const float* __restrict__ bias,
                                                  __nv_bfloat16* __restrict__ Rh,
                                                  __nv_bfloat16* __restrict__ Rl) {
    extern __shared__ __align__(16) char sm[];
    float* sBias = (float*)sm;
    char* sWh  = sm + 512;
    char* sWl  = sm + 35328;
    char* sZh0 = sm + 70144;
    char* sZl0 = sm + 87552;
    char* sZh1 = sm + 104960;
    char* sZl1 = sm + 122368;
    char* sPWh = sm + 139776;
    char* sPWl = sm + 174592;
    float* sImg = (float*)(sm + 139776);

    const int t = threadIdx.x;
    const int lane = t & 31;
    const int wid = t >> 5;
    const int wm = wid >> 2, wn = wid & 3;
    const int m0 = wm << 5, n0 = wn << 5;
    const int row0 = blockIdx.x << 6;

    {
        const uint32_t* wh32 = (const uint32_t*)Wh_g;
        const uint32_t* wl32 = (const uint32_t*)Wl_g;
        const uint32_t* ph32 = (const uint32_t*)PWh;
        const uint32_t* pl32 = (const uint32_t*)PWl;
        uint32_t* dWh = (uint32_t*)sWh;
        uint32_t* dWl = (uint32_t*)sWl;
        uint32_t* dPh = (uint32_t*)sPWh;
        uint32_t* dPl = (uint32_t*)sPWl;
        for (int idx = t; idx < 8192; idx += 256) {
            int n = idx >> 6, c2 = idx & 63;
            dWh[n * 68 + c2] = wh32[idx];
            dWl[n * 68 + c2] = wl32[idx];
            dPh[n * 68 + c2] = ph32[idx];
            dPl[n * 68 + c2] = pl32[idx];
        }
        const uint32_t* oh32 = (const uint32_t*)Oh + (size_t)row0 * 64;
        const uint32_t* ol32 = (const uint32_t*)Ol + (size_t)row0 * 64;
        uint32_t* zh = (uint32_t*)sZh0;
        uint32_t* zl = (uint32_t*)sZl0;
        for (int idx = t; idx < 4096; idx += 256) {
            int n = idx >> 6, c2 = idx & 63;
            zh[n * 68 + c2] = oh32[idx];
            zl[n * 68 + c2] = ol32[idx];
        }
        if (t < 128) sBias[t] = bias[t];
    }
    __syncthreads();

    const int g3 = lane >> 3, r8 = lane & 7;
    uint32_t aOff[2], bOff[2];
#pragma unroll
    for (int mf = 0; mf < 2; mf++)
        aOff[mf] = (uint32_t)((m0 + mf * 16 + (g3 & 1) * 8 + r8) * 136) * 2 + (g3 >> 1) * 16;
#pragma unroll
    for (int nt = 0; nt < 2; nt++)
        bOff[nt] = (uint32_t)((n0 + nt * 16 + (g3 >> 1) * 8 + r8) * 136) * 2 + (g3 & 1) * 16;

    const uint32_t zhA[2] = { smem_u32(sZh0), smem_u32(sZh1) };
    const uint32_t zlA[2] = { smem_u32(sZl0), smem_u32(sZl1) };
    const uint32_t whB = smem_u32(sWh), wlB = smem_u32(sWl);
    const uint32_t phB = smem_u32(sPWh), plB = smem_u32(sPWl);

    const int gr = lane >> 2, q2 = (lane & 3) << 1;
    float bias2[4][2];
#pragma unroll
    for (int nj = 0; nj < 4; nj++) {
        bias2[nj][0] = sBias[n0 + nj * 8 + q2];
        bias2[nj][1] = sBias[n0 + nj * 8 + q2 + 1];
    }

    float d[2][4][4], y[2][4][4], accv[2][4][4];

#define MMA_PHASE(AH, AL, BH, BL)                                                  \
    _Pragma("unroll")                                                              \
    for (int kk = 0; kk < 8; kk++) {                                               \
        uint32_t ko = kk * 32;                                                     \
        uint32_t ah0[4], ah1[4], al0[4], al1[4];                                   \
        uint32_t bh0[4], bh1[4], bl0[4], bl1[4];                                   \
        ldm4(ah0, (AH) + aOff[0] + ko); ldm4(ah1, (AH) + aOff[1] + ko);            \
        ldm4(al0, (AL) + aOff[0] + ko); ldm4(al1, (AL) + aOff[1] + ko);            \
        ldm4(bh0, (BH) + bOff[0] + ko); ldm4(bh1, (BH) + bOff[1] + ko);            \
        ldm4(bl0, (BL) + bOff[0] + ko); ldm4(bl1, (BL) + bOff[1] + ko);            \
        _Pragma("unroll")                                                          \
        for (int nj = 0; nj < 4; nj++) {                                           \
            const uint32_t* bhp = (nj < 2) ? bh0 : bh1;                            \
            const uint32_t* blp = (nj < 2) ? bl0 : bl1;                            \
            uint32_t bh_0 = bhp[(nj & 1) * 2], bh_1 = bhp[(nj & 1) * 2 + 1];       \
            uint32_t bl_0 = blp[(nj & 1) * 2], bl_1 = blp[(nj & 1) * 2 + 1];       \
            mma16816(d[0][nj], ah0, bh_0, bh_1);                                   \
            mma16816(d[1][nj], ah1, bh_0, bh_1);                                   \
            mma16816(d[0][nj], al0, bh_0, bh_1);                                   \
            mma16816(d[1][nj], al1, bh_0, bh_1);                                   \
            mma16816(d[0][nj], ah0, bl_0, bl_1);                                   \
            mma16816(d[1][nj], ah1, bl_0, bl_1);                                   \
        }                                                                          \
    }

#pragma unroll
    for (int mf = 0; mf < 2; mf++)
#pragma unroll
        for (int nj = 0; nj < 4; nj++)
#pragma unroll
            for (int i = 0; i < 4; i++) d[mf][nj][i] = 0.f;
    MMA_PHASE(zhA[0], zlA[0], phB, plB)
    __syncthreads();

#pragma unroll
    for (int mf = 0; mf < 2; mf++) {
#pragma unroll
        for (int nj = 0; nj < 4; nj++) {
            const int c = n0 + nj * 8 + q2;
            float pb0 = pbias[c], pb1 = pbias[c + 1];
#pragma unroll
            for (int hh = 0; hh < 2; hh++) {
                const int row = m0 + mf * 16 + gr + hh * 8;
                float z0 = d[mf][nj][hh * 2]     + pb0;
                float z1 = d[mf][nj][hh * 2 + 1] + pb1;
                y[mf][nj][hh * 2] = z0; y[mf][nj][hh * 2 + 1] = z1;
                *(float2*)(sImg + row * 128 + c) = make_float2(z0, z1);
                uint32_t hz = bf16x2_of(z1, z0);
                *(uint32_t*)(sZh1 + (row * 136 + c) * 2) = hz;
                *(uint32_t*)(sZl1 + (row * 136 + c) * 2) =
                    bf16x2_of(z1 - bf16hi_f(hz), z0 - bf16lo_f(hz));
            }
        }
    }
    __syncthreads();

    for (int ev = 0; ev < 16; ev++) {
        const int rb = (ev & 1) ^ 1, wb = ev & 1;
#pragma unroll
        for (int mf = 0; mf < 2; mf++)
#pragma unroll
            for (int nj = 0; nj < 4; nj++)
#pragma unroll
                for (int i = 0; i < 4; i++) d[mf][nj][i] = 0.f;
        MMA_PHASE(zhA[rb], zlA[rb], whB, wlB)

        char* zhW = wb ? sZh1 : sZh0;
        char* zlW = wb ? sZl1 : sZl0;
        const int st = ev & 3;
        const float zc = (st < 2) ? 0.125f : 0.25f;
        const float aw = (st == 1 || st == 2) ? 2.f : 1.f;
#pragma unroll
        for (int mf = 0; mf < 2; mf++) {
#pragma unroll
            for (int nj = 0; nj < 4; nj++) {
                const int c = n0 + nj * 8 + q2;
#pragma unroll
                for (int hh = 0; hh < 2; hh++) {
                    const int row = m0 + mf * 16 + gr + hh * 8;
                    float kf0 = fmaxf(d[mf][nj][hh * 2]     + bias2[nj][0], 0.f);
                    float kf1 = fmaxf(d[mf][nj][hh * 2 + 1] + bias2[nj][1], 0.f);
                    float a0 = (st == 0) ? kf0 : accv[mf][nj][hh * 2]     + aw * kf0;
                    float a1 = (st == 0) ? kf1 : accv[mf][nj][hh * 2 + 1] + aw * kf1;
                    accv[mf][nj][hh * 2] = a0; accv[mf][nj][hh * 2 + 1] = a1;
                    float z0, z1;
                    if (st < 3) {
                        z0 = y[mf][nj][hh * 2]     + zc * kf0;
                        z1 = y[mf][nj][hh * 2 + 1] + zc * kf1;
                    } else {
                        y[mf][nj][hh * 2]     += (1.f / 24.f) * a0;
                        y[mf][nj][hh * 2 + 1] += (1.f / 24.f) * a1;
                        z0 = y[mf][nj][hh * 2]; z1 = y[mf][nj][hh * 2 + 1];
                    }
                    uint32_t hz = bf16x2_of(z1, z0);
                    *(uint32_t*)(zhW + (row * 136 + c) * 2) = hz;
                    *(uint32_t*)(zlW + (row * 136 + c) * 2) =
                        bf16x2_of(z1 - bf16hi_f(hz), z0 - bf16lo_f(hz));
                }
            }
        }
        __syncthreads();
    }

    uint32_t* rh32 = (uint32_t*)Rh;
    uint32_t* rl32 = (uint32_t*)Rl;
#pragma unroll
    for (int mf = 0; mf < 2; mf++) {
#pragma unroll
        for (int nj = 0; nj < 4; nj++) {
            const int c = n0 + nj * 8 + q2;
#pragma unroll
            for (int hh = 0; hh < 2; hh++) {
                const int row = m0 + mf * 16 + gr + hh * 8;
                float2 iv = *(const float2*)(sImg + row * 128 + c);
                float r0 = y[mf][nj][hh * 2]     + iv.x;
                float r1 = y[mf][nj][hh * 2 + 1] + iv.y;
                uint32_t hz = bf16x2_of(r1, r0);
                int o = (row0 + row) * 64 + (c >> 1);
                rh32[o] = hz;
                rl32[o] = bf16x2_of(r1 - bf16hi_f(hz), r0 - bf16lo_f(hz));
            }
        }
    }
#undef MMA_PHASE
}

// ---------------- launch ----------------
extern "C" void kernel_launch(void* const* d_in, const int* in_sizes, int n_in,
                              void* d_out, int out_size) {
    const float* img   = (const float*)d_in[0];
    const int*   ptsuv = (const int*)  d_in[1];
    const float* ptsf  = (const float*)d_in[2];
    const float* wci   = (const float*)d_in[3];
    const float* bci   = (const float*)d_in[4];
    const float* wqkv  = (const float*)d_in[5];
    const float* bqkv  = (const float*)d_in[6];
    const float* wpr   = (const float*)d_in[7];
    const float* bpr   = (const float*)d_in[8];
    const float* wode  = (const float*)d_in[9];
    const float* bode  = (const float*)d_in[10];
    const float* wco   = (const float*)d_in[11];
    const float* bco   = (const float*)d_in[12];
    float* out = (float*)d_out;

    float *pqkv;
    __nv_bfloat16 *pwh, *pwl, *pfh, *pfl, *poh, *pol, *prh, *prl, *pih, *pil;
    cudaGetSymbolAddress((void**)&pqkv, g_qkv);
    cudaGetSymbolAddress((void**)&pwh,  g_wh);
    cudaGetSymbolAddress((void**)&pwl,  g_wl);
    cudaGetSymbolAddress((void**)&pfh,  g_feath);
    cudaGetSymbolAddress((void**)&pfl,  g_featl);
    cudaGetSymbolAddress((void**)&poh,  g_oh);
    cudaGetSymbolAddress((void**)&pol,  g_ol);
    cudaGetSymbolAddress((void**)&prh,  g_resh);
    cudaGetSymbolAddress((void**)&prl,  g_resl);
    cudaGetSymbolAddress((void**)&pih,  g_imgh);
    cudaGetSymbolAddress((void**)&pil,  g_imgl);

    cudaFuncSetAttribute(ode_mma,      cudaFuncAttributeMaxDynamicSharedMemorySize, ODE_SMEM);
    cudaFuncSetAttribute(bfgemm_bf,    cudaFuncAttributeMaxDynamicSharedMemorySize, GBF_SMEM);
    cudaFuncSetAttribute(bfgemm_tr_bf, cudaFuncAttributeMaxDynamicSharedMemorySize, GTR_SMEM);
    cudaFuncSetAttribute(mid_kernel,   cudaFuncAttributeMaxDynamicSharedMemorySize, MID_SMEM);
    cudaFuncSetAttribute(attn_kernel,  cudaFuncAttributeMaxDynamicSharedMemorySize, ATTN_SMEM);

    prep<<<3680, 256>>>(wci, wqkv, wpr, wode, wco, ptsf, ptsuv, img);
    // mid: scatter (32) | conv_in (128) | point-KV (256)
    mid_kernel<<<416, 256, MID_SMEM>>>(
        pih, pil, pwh + WOFF_CI, pwl + WOFF_CI, bci, pfh, pfl,
        pfh + (size_t)NPIX * 128, pfl + (size_t)NPIX * 128,
        pwh + WOFF_QKV + 128 * 128, pwl + WOFF_QKV + 128 * 128,
        bqkv + 128, pqkv + (size_t)NPIX * 384 + 128);
    // pixel qkv: M=8192, N=384, K=128
    bfgemm_bf<<<dim3(6, 64), 256, GBF_SMEM>>>(pfh, pfl, pwh + WOFF_QKV, pwl + WOFF_QKV,
                                              bqkv, pqkv, 384, 128);
    // attention (no-max softmax, f32x2 packed) -> o h/l
    attn_kernel<<<dim3(8, 128), 256, ATTN_SMEM>>>(pqkv, poh, pol);
    // fused proj + RK4 ODE -> res h/l
    ode_mma<<<128, 256, ODE_SMEM>>>(poh, pol, pwh + WOFF_PR, pwl + WOFF_PR, bpr,
                                    pwh + WOFF_ODE, pwl + WOFF_ODE, bode, prh, prl);
    // conv_out -> NCHW out
    bfgemm_tr_bf<<<dim3(4, 64), 256, GTR_SMEM>>>(prh, prl, pwh + WOFF_CO, pwl + WOFF_CO,
                                                 bco, out, 128);
}